// round 1
// baseline (speedup 1.0000x reference)
#include <cuda_runtime.h>
#include <math.h>

#define Bc 4
#define Lc 2048
#define Dc 256
#define Pc 32
#define Mc 8192
#define NCc 32
#define CHc 64
#define PIF 3.14159265358979323846f
#define INV_SQRT_P 0.17677669529663688f

// ---------------- scratch (single static device buffer, no allocs) --------
static constexpr size_t OFF_V1     = 0;            // 8192*32
static constexpr size_t OFF_OFFP   = 262144;       // 8192*32  (offset phases)
static constexpr size_t OFF_PCON   = 524288;       // 2048*32  (pos contrib to offset, incl bias)
static constexpr size_t OFF_PC     = 589824;       // 2048*32  cos(pos_phases)
static constexpr size_t OFF_PS     = 655360;       // 2048*32  sin(pos_phases)
static constexpr size_t OFF_AC     = 720896;       // 8192*64  packed [pc*v1, ps*v1] -> cumsummed in place
static constexpr size_t OFF_POSRET = 1245184;      // 8192*32
static constexpr size_t OFF_KP     = 1507328;      // 8192*32  key phases
static constexpr size_t OFF_KQ     = 1769472;      // 8192*64  [cos kp, sin kp]
static constexpr size_t OFF_SPZ    = 2293760;      // 8192*32  storage phases
static constexpr size_t OFF_U      = 2555904;      // 8192*64  [cos sp, sin sp]
static constexpr size_t OFF_VALS   = 3080192;      // 8192*256
static constexpr size_t OFF_GATE   = 5177344;      // 8192
static constexpr size_t OFF_GCUM   = 5185536;      // 8192
static constexpr size_t OFF_GV     = 5193728;      // 8192*256
static constexpr size_t OFF_XCAT   = 7290880;      // 8192*512
static constexpr size_t OFF_H      = 11485184;     // 8192*256
static constexpr size_t OFF_CSUM   = 13582336;     // 4*32*256
static constexpr size_t OFF_DS     = 13615104;     // 4*32*64*256 chunk states
static constexpr size_t OFF_COMB   = 15712256;     // 8192*256
static constexpr size_t OFF_LN     = 17809408;     // 8192*256
static constexpr size_t TOTAL_F    = 19906560;

__device__ float g_buf[TOTAL_F];

// ---------------- generic fused SGEMM: C = act(A@W + bias + addRow) + resid
// A[M,K] row-major, W[K,N] row-major. BM=64,BN=64,BK=16, 256 thr, 4x4 micro.
template<int ACT>
__global__ __launch_bounds__(256) void sgemm_k(
    const float* __restrict__ A, const float* __restrict__ W,
    const float* __restrict__ bias, const float* __restrict__ addRow,
    const float* __restrict__ resid, float* __restrict__ C,
    int N, int K)
{
    const int BM = 64, BN = 64, BK = 16;
    __shared__ float As[BK][BM];
    __shared__ float Ws[BK][BN];
    int bm = blockIdx.y * BM, bn = blockIdx.x * BN;
    int tid = threadIdx.x;
    int tRow = tid >> 4, tCol = tid & 15;
    int aRow = tid >> 2, aCol = (tid & 3) << 2;
    int wRow = tid >> 4, wCol = (tid & 15) << 2;
    float acc[4][4] = {};
    for (int k0 = 0; k0 < K; k0 += BK) {
        float4 av = *reinterpret_cast<const float4*>(A + (size_t)(bm + aRow) * K + k0 + aCol);
        As[aCol + 0][aRow] = av.x; As[aCol + 1][aRow] = av.y;
        As[aCol + 2][aRow] = av.z; As[aCol + 3][aRow] = av.w;
        float4 wv = make_float4(0.f, 0.f, 0.f, 0.f);
        int gc = bn + wCol;
        if (gc < N) wv = *reinterpret_cast<const float4*>(W + (size_t)(k0 + wRow) * N + gc);
        Ws[wRow][wCol + 0] = wv.x; Ws[wRow][wCol + 1] = wv.y;
        Ws[wRow][wCol + 2] = wv.z; Ws[wRow][wCol + 3] = wv.w;
        __syncthreads();
#pragma unroll
        for (int k = 0; k < BK; k++) {
            float ar[4], wr[4];
#pragma unroll
            for (int i = 0; i < 4; i++) ar[i] = As[k][tRow * 4 + i];
#pragma unroll
            for (int j = 0; j < 4; j++) wr[j] = Ws[k][tCol * 4 + j];
#pragma unroll
            for (int i = 0; i < 4; i++)
#pragma unroll
                for (int j = 0; j < 4; j++) acc[i][j] += ar[i] * wr[j];
        }
        __syncthreads();
    }
#pragma unroll
    for (int i = 0; i < 4; i++) {
        int row = bm + tRow * 4 + i;
        int lrow = row & (Lc - 1);
#pragma unroll
        for (int j = 0; j < 4; j++) {
            int col = bn + tCol * 4 + j;
            if (col >= N) continue;
            float v = acc[i][j];
            if (bias) v += bias[col];
            if (addRow) v += addRow[(size_t)lrow * N + col];
            if (ACT == 1) v = tanhf(v) * PIF;
            else if (ACT == 2) v = 0.5f * v * (1.0f + erff(v * 0.70710678118654752f));
            if (resid) v += resid[(size_t)row * N + col];
            C[(size_t)row * N + col] = v;
        }
    }
}

// ---------------- pos precompute: cos/sin tables + pos part of offset ------
__global__ void pos_pre_k(const float* __restrict__ ph, const float* __restrict__ w_off,
                          const float* __restrict__ b_off,
                          float* __restrict__ pc, float* __restrict__ ps,
                          float* __restrict__ pcon)
{
    int idx = blockIdx.x * blockDim.x + threadIdx.x; // L*P
    if (idx >= Lc * Pc) return;
    int l = idx >> 5, p = idx & 31;
    float s = b_off[p];
#pragma unroll
    for (int q = 0; q < Pc; q++) s += ph[l * Pc + q] * w_off[(Dc + q) * Pc + p];
    pcon[idx] = s;
    float v = ph[idx];
    pc[idx] = cosf(v);
    ps[idx] = sinf(v);
}

// ---------------- elementwise kernels -------------------------------------
__global__ void pack_ac_k(const float* __restrict__ v1, const float* __restrict__ pc,
                          const float* __restrict__ ps, float* __restrict__ ac)
{
    int idx = blockIdx.x * blockDim.x + threadIdx.x; // M*P
    int m = idx >> 5, p = idx & 31, l = m & (Lc - 1);
    float v = v1[idx];
    ac[(size_t)m * 64 + p]      = pc[l * Pc + p] * v;
    ac[(size_t)m * 64 + 32 + p] = ps[l * Pc + p] * v;
}

__global__ void posret_k(const float* __restrict__ offp, const float* __restrict__ pc,
                         const float* __restrict__ ps, const float* __restrict__ ac,
                         float* __restrict__ pr)
{
    int idx = blockIdx.x * blockDim.x + threadIdx.x; // M*P
    int m = idx >> 5, p = idx & 31, l = m & (Lc - 1);
    float o = offp[idx];
    float oc = cosf(o), os = sinf(o);
    float pcv = pc[l * Pc + p], psv = ps[l * Pc + p];
    float qc = pcv * oc - psv * os;
    float qs = psv * oc + pcv * os;
    float Cc = ac[(size_t)m * 64 + p], Cs = ac[(size_t)m * 64 + 32 + p];
    pr[idx] = (Cc * qc + Cs * qs) * INV_SQRT_P;
}

__global__ void cos_sin_pack_k(const float* __restrict__ ph, float* __restrict__ out)
{
    int idx = blockIdx.x * blockDim.x + threadIdx.x; // M*P
    int m = idx >> 5, p = idx & 31;
    float v = ph[idx];
    out[(size_t)m * 64 + p]      = cosf(v);
    out[(size_t)m * 64 + 32 + p] = sinf(v);
}

__global__ void gv_mul_k(const float* __restrict__ vals, const float* __restrict__ gate,
                         float* __restrict__ gv)
{
    int idx = blockIdx.x * blockDim.x + threadIdx.x; // M*D
    gv[idx] = vals[idx] * gate[idx >> 8];
}

__global__ void xcat_fill_k(const float* __restrict__ x, float* __restrict__ xc)
{
    int idx = blockIdx.x * blockDim.x + threadIdx.x; // M*D
    int m = idx >> 8, d = idx & 255, l = m & (Lc - 1);
    xc[(size_t)m * 512 + d] = x[idx];
    xc[(size_t)m * 512 + 256 + d] *= 1.0f / (float)(l + 1);
}

// ---------------- gate dot + sigmoid (N=1 GEMM) ---------------------------
__global__ void gate_k(const float* __restrict__ x, const float* __restrict__ w,
                       const float* __restrict__ b, float* __restrict__ gate)
{
    int warp = (blockIdx.x * blockDim.x + threadIdx.x) >> 5;
    int lane = threadIdx.x & 31;
    if (warp >= Mc) return;
    const float* xr = x + (size_t)warp * Dc;
    float s = 0.f;
#pragma unroll
    for (int i = 0; i < Dc / 32; i++) s += xr[lane + 32 * i] * w[lane + 32 * i];
#pragma unroll
    for (int o = 16; o; o >>= 1) s += __shfl_xor_sync(0xffffffffu, s, o);
    if (lane == 0) gate[warp] = 1.0f / (1.0f + expf(-(s + b[0])));
}

// ---------------- chunked scans (3 passes, generic over F) ----------------
__global__ void scan_chunk_sums_k(const float* __restrict__ in, float* __restrict__ csum,
                                  int F, int inStride)
{
    int bc = blockIdx.x, b = bc / NCc, c = bc % NCc, f = threadIdx.x;
    const float* p = in + ((size_t)b * Lc + c * CHc) * inStride + f;
    float s = 0.f;
    for (int i = 0; i < CHc; i++) s += p[(size_t)i * inStride];
    csum[(size_t)bc * F + f] = s;
}

__global__ void scan_prefix_k(float* __restrict__ csum, int F)
{
    int b = blockIdx.x, f = threadIdx.x;
    float carry = 0.f;
    for (int c = 0; c < NCc; c++) {
        size_t idx = ((size_t)b * NCc + c) * F + f;
        float v = csum[idx];
        csum[idx] = carry;
        carry += v;
    }
}

__global__ void scan_apply_k(const float* __restrict__ in, const float* __restrict__ csum,
                             float* __restrict__ out, int F, int inStride, int outStride)
{
    int bc = blockIdx.x, b = bc / NCc, c = bc % NCc, f = threadIdx.x;
    float carry = csum[(size_t)bc * F + f];
    const float* p = in + ((size_t)b * Lc + c * CHc) * inStride + f;
    float* q = out + ((size_t)b * Lc + c * CHc) * outStride + f;
    for (int i = 0; i < CHc; i++) {
        carry += p[(size_t)i * inStride];
        q[(size_t)i * outStride] = carry;
    }
}

// ---------------- gate cumsum (one warp per batch) ------------------------
__global__ void gate_scan_k(const float* __restrict__ g, float* __restrict__ gc)
{
    int b = blockIdx.x, t = threadIdx.x; // 32 threads
    const float* p = g + b * Lc + t * CHc;
    float s = 0.f;
    for (int i = 0; i < CHc; i++) s += p[i];
    float xv = s;
#pragma unroll
    for (int o = 1; o < 32; o <<= 1) {
        float v = __shfl_up_sync(0xffffffffu, xv, o);
        if (t >= o) xv += v;
    }
    float carry = xv - s;
    float* q = gc + b * Lc + t * CHc;
    for (int i = 0; i < CHc; i++) { carry += p[i]; q[i] = carry; }
}

// ---------------- chunk state delta: dS[bc] = U_chunk^T @ GV_chunk --------
__global__ __launch_bounds__(256) void chunk_delta_k(const float* __restrict__ U,
                                                     const float* __restrict__ GV,
                                                     float* __restrict__ dS)
{
    __shared__ float Us[64][65];
    __shared__ float Gs[64][65];
    int bc = blockIdx.x;                 // b*32 + c
    size_t rowbase = (size_t)bc * 64;    // = b*L + c*64
    int tid = threadIdx.x;
#pragma unroll
    for (int i = 0; i < 16; i++) {
        int idx = tid + i * 256; int t = idx >> 6, f = idx & 63;
        Us[t][f] = U[(rowbase + t) * 64 + f];
    }
    int tR = tid >> 4, tC = tid & 15;
    for (int dt = 0; dt < 4; dt++) {
#pragma unroll
        for (int i = 0; i < 16; i++) {
            int idx = tid + i * 256; int t = idx >> 6, d = idx & 63;
            Gs[t][d] = GV[(rowbase + t) * 256 + dt * 64 + d];
        }
        __syncthreads();
        float acc[4][4] = {};
        for (int t = 0; t < 64; t++) {
            float ur[4], gr[4];
#pragma unroll
            for (int i = 0; i < 4; i++) ur[i] = Us[t][tR * 4 + i];
#pragma unroll
            for (int j = 0; j < 4; j++) gr[j] = Gs[t][tC * 4 + j];
#pragma unroll
            for (int i = 0; i < 4; i++)
#pragma unroll
                for (int j = 0; j < 4; j++) acc[i][j] += ur[i] * gr[j];
        }
        __syncthreads();
#pragma unroll
        for (int i = 0; i < 4; i++)
#pragma unroll
            for (int j = 0; j < 4; j++) {
                int f = tR * 4 + i, d = dt * 64 + tC * 4 + j;
                dS[((size_t)bc * 64 + f) * 256 + d] = acc[i][j];
            }
    }
}

// ---------------- exclusive prefix of chunk states over chunks ------------
__global__ void state_prefix_k(float* __restrict__ dS)
{
    int idx = blockIdx.x * blockDim.x + threadIdx.x; // B*64*256
    int b = idx / (64 * 256);
    int fd = idx % (64 * 256);
    float carry = 0.f;
    for (int c = 0; c < NCc; c++) {
        size_t o = ((size_t)(b * NCc + c)) * 64 * 256 + fd;
        float v = dS[o];
        dS[o] = carry;
        carry += v;
    }
}

// ---------------- kv pass3: r = Kq@Spre + causal_local, scaled, += comb ---
__global__ __launch_bounds__(256) void kv_pass3_k(const float* __restrict__ Kq,
                                                  const float* __restrict__ U,
                                                  const float* __restrict__ GV,
                                                  const float* __restrict__ Spre,
                                                  const float* __restrict__ gcum,
                                                  float* __restrict__ comb)
{
    __shared__ float Ks[64][65];
    __shared__ float SU[64][65];  // holds U, then local scores
    __shared__ float Bs[64][33];
    int bc = blockIdx.x;
    size_t rowbase = (size_t)bc * 64;
    int tid = threadIdx.x;
#pragma unroll
    for (int i = 0; i < 16; i++) {
        int idx = tid + i * 256; int t = idx >> 6, f = idx & 63;
        Ks[t][f] = Kq[(rowbase + t) * 64 + f];
        SU[t][f] = U[(rowbase + t) * 64 + f];
    }
    __syncthreads();
    float sl[16];
#pragma unroll
    for (int i = 0; i < 16; i++) {
        int idx = tid + i * 256; int l = idx >> 6, t = idx & 63;
        float s = 0.f;
        if (t <= l) {
#pragma unroll
            for (int f = 0; f < 64; f++) s += Ks[l][f] * SU[t][f];
        }
        sl[i] = s;
    }
    __syncthreads();
#pragma unroll
    for (int i = 0; i < 16; i++) {
        int idx = tid + i * 256; int l = idx >> 6, t = idx & 63;
        SU[l][t] = sl[i];
    }
    __syncthreads();
    int tRow = tid >> 4, tCol = tid & 15;
    int l0 = tRow * 4;
    float scl[4];
#pragma unroll
    for (int i = 0; i < 4; i++) {
        float gc = gcum[rowbase + l0 + i];
        scl[i] = rsqrtf(fmaxf(gc, 1.0f)) * INV_SQRT_P;
    }
    for (int dt = 0; dt < 8; dt++) {
        int d0 = dt * 32;
#pragma unroll
        for (int i = 0; i < 8; i++) {
            int idx = tid + i * 256; int t = idx >> 5, d = idx & 31;
            Bs[t][d] = GV[(rowbase + t) * 256 + d0 + d];
        }
        __syncthreads();
        float acc[4][2] = {};
        for (int t = 0; t < 64; t++) {
            float b0 = Bs[t][tCol * 2], b1 = Bs[t][tCol * 2 + 1];
#pragma unroll
            for (int i = 0; i < 4; i++) {
                float s = SU[l0 + i][t];
                acc[i][0] += s * b0;
                acc[i][1] += s * b1;
            }
        }
        __syncthreads();
#pragma unroll
        for (int i = 0; i < 8; i++) {
            int idx = tid + i * 256; int f = idx >> 5, d = idx & 31;
            Bs[f][d] = Spre[((size_t)bc * 64 + f) * 256 + d0 + d];
        }
        __syncthreads();
        for (int f = 0; f < 64; f++) {
            float b0 = Bs[f][tCol * 2], b1 = Bs[f][tCol * 2 + 1];
#pragma unroll
            for (int i = 0; i < 4; i++) {
                float k = Ks[l0 + i][f];
                acc[i][0] += k * b0;
                acc[i][1] += k * b1;
            }
        }
        __syncthreads();
#pragma unroll
        for (int i = 0; i < 4; i++)
#pragma unroll
            for (int j = 0; j < 2; j++) {
                size_t o = (rowbase + l0 + i) * 256 + d0 + tCol * 2 + j;
                comb[o] += acc[i][j] * scl[i];
            }
    }
}

// ---------------- layernorm over D=256 ------------------------------------
__global__ __launch_bounds__(256) void ln_k(const float* __restrict__ c,
                                            const float* __restrict__ g,
                                            const float* __restrict__ bt,
                                            float* __restrict__ out)
{
    int m = blockIdx.x, t = threadIdx.x;
    float v = c[(size_t)m * 256 + t];
    float s = v, s2 = v * v;
#pragma unroll
    for (int o = 16; o; o >>= 1) {
        s += __shfl_xor_sync(0xffffffffu, s, o);
        s2 += __shfl_xor_sync(0xffffffffu, s2, o);
    }
    __shared__ float ws[8], ws2[8];
    int w = t >> 5, lane = t & 31;
    if (lane == 0) { ws[w] = s; ws2[w] = s2; }
    __syncthreads();
    if (w == 0) {
        s = (lane < 8) ? ws[lane] : 0.f;
        s2 = (lane < 8) ? ws2[lane] : 0.f;
#pragma unroll
        for (int o = 4; o; o >>= 1) {
            s += __shfl_xor_sync(0xffffffffu, s, o);
            s2 += __shfl_xor_sync(0xffffffffu, s2, o);
        }
        if (lane == 0) { ws[0] = s; ws2[0] = s2; }
    }
    __syncthreads();
    float mean = ws[0] * (1.0f / 256.0f);
    float var = ws2[0] * (1.0f / 256.0f) - mean * mean;
    out[(size_t)m * 256 + t] = (v - mean) * rsqrtf(var + 1e-5f) * g[t] + bt[t];
}

// ---------------- host launch ---------------------------------------------
extern "C" void kernel_launch(void* const* d_in, const int* in_sizes, int n_in,
                              void* d_out, int out_size)
{
    (void)in_sizes; (void)n_in; (void)out_size;
    const float* x        = (const float*)d_in[0];
    const float* pos_ph   = (const float*)d_in[1];
    const float* w_mem1v  = (const float*)d_in[2];
    const float* b_mem1v  = (const float*)d_in[3];
    const float* w_mem1o  = (const float*)d_in[4];
    const float* b_mem1o  = (const float*)d_in[5];
    const float* w_off    = (const float*)d_in[6];
    const float* b_off    = (const float*)d_in[7];
    const float* w_key    = (const float*)d_in[8];
    const float* b_key    = (const float*)d_in[9];
    const float* w_val    = (const float*)d_in[10];
    const float* b_val    = (const float*)d_in[11];
    const float* w_sk1    = (const float*)d_in[12];
    const float* b_sk1    = (const float*)d_in[13];
    const float* w_sk2    = (const float*)d_in[14];
    const float* b_sk2    = (const float*)d_in[15];
    const float* w_gate   = (const float*)d_in[16];
    const float* b_gate   = (const float*)d_in[17];
    const float* ln_g     = (const float*)d_in[18];
    const float* ln_b     = (const float*)d_in[19];
    const float* w_out    = (const float*)d_in[20];
    const float* b_out    = (const float*)d_in[21];
    float* out = (float*)d_out;

    float* buf = nullptr;
    cudaGetSymbolAddress((void**)&buf, g_buf);
    float* v1    = buf + OFF_V1;
    float* offp  = buf + OFF_OFFP;
    float* pcon  = buf + OFF_PCON;
    float* pc    = buf + OFF_PC;
    float* ps    = buf + OFF_PS;
    float* ac    = buf + OFF_AC;
    float* pr    = buf + OFF_POSRET;
    float* kp    = buf + OFF_KP;
    float* kq    = buf + OFF_KQ;
    float* spz   = buf + OFF_SPZ;
    float* u     = buf + OFF_U;
    float* vals  = buf + OFF_VALS;
    float* gate  = buf + OFF_GATE;
    float* gcum  = buf + OFF_GCUM;
    float* gv    = buf + OFF_GV;
    float* xcat  = buf + OFF_XCAT;
    float* h     = buf + OFF_H;
    float* csum  = buf + OFF_CSUM;
    float* dS    = buf + OFF_DS;
    float* comb  = buf + OFF_COMB;
    float* lnb   = buf + OFF_LN;

    dim3 gN32(1, Mc / 64), gN256(4, Mc / 64);

    // pos tables + pos part of offset
    pos_pre_k<<<(Lc * Pc) / 256, 256>>>(pos_ph, w_off, b_off, pc, ps, pcon);
    // v1 = x@w_mem1v + b
    sgemm_k<0><<<gN32, 256>>>(x, w_mem1v, b_mem1v, nullptr, nullptr, v1, Pc, Dc);
    // offset = tanh(x@w_off[:D] + pcon)*pi
    sgemm_k<1><<<gN32, 256>>>(x, w_off, nullptr, pcon, nullptr, offp, Pc, Dc);
    // mem1 cumsums (packed cos/sin channels)
    pack_ac_k<<<(Mc * Pc) / 256, 256>>>(v1, pc, ps, ac);
    scan_chunk_sums_k<<<Bc * NCc, 64>>>(ac, csum, 64, 64);
    scan_prefix_k<<<Bc, 64>>>(csum, 64);
    scan_apply_k<<<Bc * NCc, 64>>>(ac, csum, ac, 64, 64, 64);
    // pos_ret
    posret_k<<<(Mc * Pc) / 256, 256>>>(offp, pc, ps, ac, pr);
    // comb = pos_ret @ w_mem1o + b
    sgemm_k<0><<<gN256, 256>>>(pr, w_mem1o, b_mem1o, nullptr, nullptr, comb, Dc, Pc);
    // key phases -> kq
    sgemm_k<1><<<gN32, 256>>>(x, w_key, b_key, nullptr, nullptr, kp, Pc, Dc);
    cos_sin_pack_k<<<(Mc * Pc) / 256, 256>>>(kp, kq);
    // values, gate, gated values
    sgemm_k<0><<<gN256, 256>>>(x, w_val, b_val, nullptr, nullptr, vals, Dc, Dc);
    gate_k<<<Mc / 8, 256>>>(x, w_gate, b_gate, gate);
    gv_mul_k<<<(Mc * Dc) / 256, 256>>>(vals, gate, gv);
    gate_scan_k<<<Bc, 32>>>(gate, gcum);
    // context avg -> xcat = [x, cumsum(x)/pos]
    scan_chunk_sums_k<<<Bc * NCc, 256>>>(x, csum, 256, 256);
    scan_prefix_k<<<Bc, 256>>>(csum, 256);
    scan_apply_k<<<Bc * NCc, 256>>>(x, csum, xcat + 256, 256, 256, 512);
    xcat_fill_k<<<(Mc * Dc) / 256, 256>>>(x, xcat);
    // h = gelu(xcat@w_sk1 + b)
    sgemm_k<2><<<gN256, 256>>>(xcat, w_sk1, b_sk1, nullptr, nullptr, h, Dc, 2 * Dc);
    // storage phases -> u
    sgemm_k<1><<<gN32, 256>>>(h, w_sk2, b_sk2, nullptr, nullptr, spz, Pc, Dc);
    cos_sin_pack_k<<<(Mc * Pc) / 256, 256>>>(spz, u);
    // chunked linear attention
    chunk_delta_k<<<Bc * NCc, 256>>>(u, gv, dS);
    state_prefix_k<<<(Bc * 64 * 256) / 256, 256>>>(dS);
    kv_pass3_k<<<Bc * NCc, 256>>>(kq, u, gv, dS, gcum, comb);
    // layernorm + output projection + residual
    ln_k<<<Mc, 256>>>(comb, ln_g, ln_b, lnb);
    sgemm_k<0><<<gN256, 256>>>(lnb, w_out, b_out, nullptr, x, out, Dc, Dc);
}

// round 3
// speedup vs baseline: 1.5713x; 1.5713x over previous
#include <cuda_runtime.h>
#include <cstdint>
#include <math.h>

#define Bc 4
#define Lc 2048
#define Dc 256
#define Pc 32
#define Mc 8192
#define NCc 32
#define CHc 64
#define PIF 3.14159265358979323846f
#define INV_SQRT_P 0.17677669529663688f

// ---------------- scratch (single static device buffer, no allocs) --------
static constexpr size_t OFF_V1     = 0;            // 8192*32
static constexpr size_t OFF_OFFP   = 262144;       // 8192*32
static constexpr size_t OFF_PCON   = 524288;       // 2048*32
static constexpr size_t OFF_PC     = 589824;       // 2048*32
static constexpr size_t OFF_PS     = 655360;       // 2048*32
static constexpr size_t OFF_AC     = 720896;       // 8192*64
static constexpr size_t OFF_POSRET = 1245184;      // 8192*32
static constexpr size_t OFF_KQ     = 1769472;      // 8192*64
static constexpr size_t OFF_U      = 2555904;      // 8192*64
static constexpr size_t OFF_GATE   = 5177344;      // 8192
static constexpr size_t OFF_GCUM   = 5185536;      // 8192
static constexpr size_t OFF_GV     = 5193728;      // 8192*256
static constexpr size_t OFF_XCAT   = 7290880;      // 8192*512
static constexpr size_t OFF_H      = 11485184;     // 8192*256
static constexpr size_t OFF_CSUM   = 13582336;     // 4*32*256
static constexpr size_t OFF_DS     = 13615104;     // 4*32*64*256
static constexpr size_t OFF_COMB   = 15712256;     // 8192*256
static constexpr size_t OFF_LN     = 17809408;     // 8192*256
static constexpr size_t TOTAL_F    = 19906560;

__device__ float g_buf[TOTAL_F];

// ---------------- tf32 mma helpers ----------------------------------------
__device__ __forceinline__ uint32_t f2tf(float f) {
    uint32_t u;
    asm("cvt.rna.tf32.f32 %0, %1;" : "=r"(u) : "f"(f));
    return u;
}

__device__ __forceinline__ void mma8(float* c, const uint32_t* a, const uint32_t* b) {
    asm volatile(
        "mma.sync.aligned.m16n8k8.row.col.f32.tf32.tf32.f32 "
        "{%0,%1,%2,%3},{%4,%5,%6,%7},{%8,%9},{%0,%1,%2,%3};"
        : "+f"(c[0]), "+f"(c[1]), "+f"(c[2]), "+f"(c[3])
        : "r"(a[0]), "r"(a[1]), "r"(a[2]), "r"(a[3]), "r"(b[0]), "r"(b[1]));
}

// ---------------- tensor-core GEMM -----------------------------------------
// C = act(A@W + bias [+ addRow]) [+ resid]
// A[M,K] rm, W[K,N] rm. 256 threads, warp layout 4(M)x2(N).
// BM = 4*MT*16, BN = 2*NT*8. BK=32.
// ACT: 0 none, 1 tanh*pi, 2 gelu, 3 tanh*pi->cos/sin packed (stride 64),
//      4 (v+bias)*addRow[row] (gate fuse)
// SPLIT: 1 -> 3-mma tf32 split correction (near-fp32 accuracy)
template<int BM, int BN, int MT, int NT, int ACT, int SPLIT>
__global__ __launch_bounds__(256) void tgemm_k(
    const float* __restrict__ A, const float* __restrict__ W,
    const float* __restrict__ bias, const float* __restrict__ addRow,
    const float* __restrict__ resid, float* __restrict__ C,
    int N, int K)
{
    static_assert(BM == 4 * MT * 16 && BN == 2 * NT * 8, "tile mismatch");
    const int BK = 32;
    __shared__ float As[BM][BK + 4];
    __shared__ float Ws[BK][BN + 8];
    int tid = threadIdx.x;
    int warp = tid >> 5, lane = tid & 31;
    int wm = warp >> 1, wn = warp & 1;
    int g = lane >> 2, tig = lane & 3;
    int bm = blockIdx.y * BM, bn = blockIdx.x * BN;

    float acc[MT][NT][4] = {};

    for (int k0 = 0; k0 < K; k0 += BK) {
        constexpr int AF4 = BM * BK / 4 / 256;
#pragma unroll
        for (int i = 0; i < AF4; i++) {
            int id = tid + 256 * i;
            int r = id >> 3, c4 = (id & 7) << 2;
            float4 v = *reinterpret_cast<const float4*>(A + (size_t)(bm + r) * K + k0 + c4);
            if (!SPLIT) {
                v.x = __uint_as_float(f2tf(v.x)); v.y = __uint_as_float(f2tf(v.y));
                v.z = __uint_as_float(f2tf(v.z)); v.w = __uint_as_float(f2tf(v.w));
            }
            *reinterpret_cast<float4*>(&As[r][c4]) = v;
        }
        constexpr int WF4 = BK * BN / 4 / 256;
#pragma unroll
        for (int i = 0; i < WF4; i++) {
            int id = tid + 256 * i;
            int r = id / (BN / 4), c4 = (id % (BN / 4)) << 2;
            float4 v = *reinterpret_cast<const float4*>(W + (size_t)(k0 + r) * N + bn + c4);
            if (!SPLIT) {
                v.x = __uint_as_float(f2tf(v.x)); v.y = __uint_as_float(f2tf(v.y));
                v.z = __uint_as_float(f2tf(v.z)); v.w = __uint_as_float(f2tf(v.w));
            }
            *reinterpret_cast<float4*>(&Ws[r][c4]) = v;
        }
        __syncthreads();
#pragma unroll
        for (int ks = 0; ks < 4; ks++) {
            int kk = ks * 8;
            uint32_t ah[MT][4], al[MT][4];
#pragma unroll
            for (int mt = 0; mt < MT; mt++) {
                int r0 = wm * MT * 16 + mt * 16 + g;
                float f0 = As[r0][kk + tig],     f1 = As[r0 + 8][kk + tig];
                float f2 = As[r0][kk + tig + 4], f3 = As[r0 + 8][kk + tig + 4];
                if (SPLIT) {
                    ah[mt][0] = f2tf(f0); al[mt][0] = f2tf(f0 - __uint_as_float(ah[mt][0]));
                    ah[mt][1] = f2tf(f1); al[mt][1] = f2tf(f1 - __uint_as_float(ah[mt][1]));
                    ah[mt][2] = f2tf(f2); al[mt][2] = f2tf(f2 - __uint_as_float(ah[mt][2]));
                    ah[mt][3] = f2tf(f3); al[mt][3] = f2tf(f3 - __uint_as_float(ah[mt][3]));
                } else {
                    ah[mt][0] = __float_as_uint(f0); ah[mt][1] = __float_as_uint(f1);
                    ah[mt][2] = __float_as_uint(f2); ah[mt][3] = __float_as_uint(f3);
                }
            }
            uint32_t bh[NT][2], bl[NT][2];
#pragma unroll
            for (int nt = 0; nt < NT; nt++) {
                int cn = wn * NT * 8 + nt * 8 + g;
                float f0 = Ws[kk + tig][cn], f1 = Ws[kk + tig + 4][cn];
                if (SPLIT) {
                    bh[nt][0] = f2tf(f0); bl[nt][0] = f2tf(f0 - __uint_as_float(bh[nt][0]));
                    bh[nt][1] = f2tf(f1); bl[nt][1] = f2tf(f1 - __uint_as_float(bh[nt][1]));
                } else {
                    bh[nt][0] = __float_as_uint(f0); bh[nt][1] = __float_as_uint(f1);
                }
            }
#pragma unroll
            for (int mt = 0; mt < MT; mt++)
#pragma unroll
                for (int nt = 0; nt < NT; nt++) {
                    mma8(acc[mt][nt], ah[mt], bh[nt]);
                    if (SPLIT) {
                        mma8(acc[mt][nt], al[mt], bh[nt]);
                        mma8(acc[mt][nt], ah[mt], bl[nt]);
                    }
                }
        }
        __syncthreads();
    }

#pragma unroll
    for (int mt = 0; mt < MT; mt++)
#pragma unroll
        for (int nt = 0; nt < NT; nt++) {
            int r0 = bm + wm * MT * 16 + mt * 16 + g;
            int col = bn + wn * NT * 8 + nt * 8 + 2 * tig;
#pragma unroll
            for (int h2 = 0; h2 < 2; h2++) {
                int row = r0 + h2 * 8;
                int lrow = row & (Lc - 1);
                float v0 = acc[mt][nt][h2 * 2 + 0];
                float v1 = acc[mt][nt][h2 * 2 + 1];
                if (bias) { v0 += bias[col]; v1 += bias[col + 1]; }
                if (ACT == 4) {
                    float gt = addRow[row];
                    v0 *= gt; v1 *= gt;
                } else if (addRow) {
                    v0 += addRow[(size_t)lrow * N + col];
                    v1 += addRow[(size_t)lrow * N + col + 1];
                }
                if (ACT == 1) { v0 = tanhf(v0) * PIF; v1 = tanhf(v1) * PIF; }
                else if (ACT == 2) {
                    v0 = 0.5f * v0 * (1.0f + erff(v0 * 0.70710678118654752f));
                    v1 = 0.5f * v1 * (1.0f + erff(v1 * 0.70710678118654752f));
                }
                if (ACT == 3) {
                    v0 = tanhf(v0) * PIF; v1 = tanhf(v1) * PIF;
                    C[(size_t)row * 64 + col]          = cosf(v0);
                    C[(size_t)row * 64 + 32 + col]     = sinf(v0);
                    C[(size_t)row * 64 + col + 1]      = cosf(v1);
                    C[(size_t)row * 64 + 32 + col + 1] = sinf(v1);
                } else {
                    if (resid) {
                        v0 += resid[(size_t)row * N + col];
                        v1 += resid[(size_t)row * N + col + 1];
                    }
                    float2 o = make_float2(v0, v1);
                    *reinterpret_cast<float2*>(&C[(size_t)row * N + col]) = o;
                }
            }
        }
}

// ---------------- pos precompute -------------------------------------------
__global__ void pos_pre_k(const float* __restrict__ ph, const float* __restrict__ w_off,
                          const float* __restrict__ b_off,
                          float* __restrict__ pc, float* __restrict__ ps,
                          float* __restrict__ pcon)
{
    int idx = blockIdx.x * blockDim.x + threadIdx.x;
    if (idx >= Lc * Pc) return;
    int l = idx >> 5, p = idx & 31;
    float s = b_off[p];
#pragma unroll
    for (int q = 0; q < Pc; q++) s += ph[l * Pc + q] * w_off[(Dc + q) * Pc + p];
    pcon[idx] = s;
    float v = ph[idx];
    pc[idx] = cosf(v);
    ps[idx] = sinf(v);
}

// ---------------- elementwise kernels --------------------------------------
__global__ void pack_ac_k(const float* __restrict__ v1, const float* __restrict__ pc,
                          const float* __restrict__ ps, float* __restrict__ ac)
{
    int idx = blockIdx.x * blockDim.x + threadIdx.x;
    int m = idx >> 5, p = idx & 31, l = m & (Lc - 1);
    float v = v1[idx];
    ac[(size_t)m * 64 + p]      = pc[l * Pc + p] * v;
    ac[(size_t)m * 64 + 32 + p] = ps[l * Pc + p] * v;
}

__global__ void posret_k(const float* __restrict__ offp, const float* __restrict__ pc,
                         const float* __restrict__ ps, const float* __restrict__ ac,
                         float* __restrict__ pr)
{
    int idx = blockIdx.x * blockDim.x + threadIdx.x;
    int m = idx >> 5, p = idx & 31, l = m & (Lc - 1);
    float o = offp[idx];
    float oc = cosf(o), os = sinf(o);
    float pcv = pc[l * Pc + p], psv = ps[l * Pc + p];
    float qc = pcv * oc - psv * os;
    float qs = psv * oc + pcv * os;
    float Cc = ac[(size_t)m * 64 + p], Cs = ac[(size_t)m * 64 + 32 + p];
    pr[idx] = (Cc * qc + Cs * qs) * INV_SQRT_P;
}

__global__ void xcat_fill_k(const float* __restrict__ x, float* __restrict__ xc)
{
    int idx = blockIdx.x * blockDim.x + threadIdx.x;
    int m = idx >> 8, d = idx & 255, l = m & (Lc - 1);
    xc[(size_t)m * 512 + d] = x[idx];
    xc[(size_t)m * 512 + 256 + d] *= 1.0f / (float)(l + 1);
}

__global__ void gate_k(const float* __restrict__ x, const float* __restrict__ w,
                       const float* __restrict__ b, float* __restrict__ gate)
{
    int warp = (blockIdx.x * blockDim.x + threadIdx.x) >> 5;
    int lane = threadIdx.x & 31;
    if (warp >= Mc) return;
    const float* xr = x + (size_t)warp * Dc;
    float s = 0.f;
#pragma unroll
    for (int i = 0; i < Dc / 32; i++) s += xr[lane + 32 * i] * w[lane + 32 * i];
#pragma unroll
    for (int o = 16; o; o >>= 1) s += __shfl_xor_sync(0xffffffffu, s, o);
    if (lane == 0) gate[warp] = 1.0f / (1.0f + expf(-(s + b[0])));
}

// ---------------- chunked scans --------------------------------------------
__global__ void scan_chunk_sums_k(const float* __restrict__ in, float* __restrict__ csum,
                                  int F, int inStride)
{
    int bc = blockIdx.x, b = bc / NCc, c = bc % NCc, f = threadIdx.x;
    const float* p = in + ((size_t)b * Lc + c * CHc) * inStride + f;
    float s = 0.f;
    for (int i = 0; i < CHc; i++) s += p[(size_t)i * inStride];
    csum[(size_t)bc * F + f] = s;
}

__global__ void scan_prefix_k(float* __restrict__ csum, int F)
{
    int b = blockIdx.x, f = threadIdx.x;
    float carry = 0.f;
    for (int c = 0; c < NCc; c++) {
        size_t idx = ((size_t)b * NCc + c) * F + f;
        float v = csum[idx];
        csum[idx] = carry;
        carry += v;
    }
}

__global__ void scan_apply_k(const float* __restrict__ in, const float* __restrict__ csum,
                             float* __restrict__ out, int F, int inStride, int outStride)
{
    int bc = blockIdx.x, b = bc / NCc, c = bc % NCc, f = threadIdx.x;
    float carry = csum[(size_t)bc * F + f];
    const float* p = in + ((size_t)b * Lc + c * CHc) * inStride + f;
    float* q = out + ((size_t)b * Lc + c * CHc) * outStride + f;
    for (int i = 0; i < CHc; i++) {
        carry += p[(size_t)i * inStride];
        q[(size_t)i * outStride] = carry;
    }
}

__global__ void gate_scan_k(const float* __restrict__ g, float* __restrict__ gc)
{
    int b = blockIdx.x, t = threadIdx.x;
    const float* p = g + b * Lc + t * CHc;
    float s = 0.f;
    for (int i = 0; i < CHc; i++) s += p[i];
    float xv = s;
#pragma unroll
    for (int o = 1; o < 32; o <<= 1) {
        float v = __shfl_up_sync(0xffffffffu, xv, o);
        if (t >= o) xv += v;
    }
    float carry = xv - s;
    float* q = gc + b * Lc + t * CHc;
    for (int i = 0; i < CHc; i++) { carry += p[i]; q[i] = carry; }
}

// ---------------- chunk state delta via tf32 mma ---------------------------
// dS[bc][f][d] = sum_t U[t][f]*GV[t][d]   (f=64, d=256, t=64)
__global__ __launch_bounds__(256) void chunk_delta_k(const float* __restrict__ U,
                                                     const float* __restrict__ GV,
                                                     float* __restrict__ dS)
{
    __shared__ float Us[64][72];
    __shared__ float Gs[64][72];
    int bc = blockIdx.x;
    size_t rowbase = (size_t)bc * 64;
    int tid = threadIdx.x;
    int warp = tid >> 5, lane = tid & 31;
    int wm = warp >> 2, wn = warp & 3;      // 2 x 4
    int g = lane >> 2, tig = lane & 3;

    // load U (cvt to tf32 at store)
#pragma unroll
    for (int i = 0; i < 4; i++) {
        int id = tid + 256 * i;
        int t = id >> 4, f = (id & 15) << 2;
        float4 v = *reinterpret_cast<const float4*>(U + (rowbase + t) * 64 + f);
        v.x = __uint_as_float(f2tf(v.x)); v.y = __uint_as_float(f2tf(v.y));
        v.z = __uint_as_float(f2tf(v.z)); v.w = __uint_as_float(f2tf(v.w));
        *reinterpret_cast<float4*>(&Us[t][f]) = v;
    }

    for (int dt = 0; dt < 4; dt++) {
        __syncthreads();
#pragma unroll
        for (int i = 0; i < 4; i++) {
            int id = tid + 256 * i;
            int t = id >> 4, d = (id & 15) << 2;
            float4 v = *reinterpret_cast<const float4*>(GV + (rowbase + t) * 256 + dt * 64 + d);
            v.x = __uint_as_float(f2tf(v.x)); v.y = __uint_as_float(f2tf(v.y));
            v.z = __uint_as_float(f2tf(v.z)); v.w = __uint_as_float(f2tf(v.w));
            *reinterpret_cast<float4*>(&Gs[t][d]) = v;
        }
        __syncthreads();

        float acc[2][2][4] = {};
#pragma unroll
        for (int ks = 0; ks < 8; ks++) {
            int kk = ks * 8;
            uint32_t a[2][4], b[2][2];
#pragma unroll
            for (int mt = 0; mt < 2; mt++) {
                int f0 = wm * 32 + mt * 16 + g;
                a[mt][0] = __float_as_uint(Us[kk + tig][f0]);
                a[mt][1] = __float_as_uint(Us[kk + tig][f0 + 8]);
                a[mt][2] = __float_as_uint(Us[kk + tig + 4][f0]);
                a[mt][3] = __float_as_uint(Us[kk + tig + 4][f0 + 8]);
            }
#pragma unroll
            for (int nt = 0; nt < 2; nt++) {
                int d0 = wn * 16 + nt * 8 + g;
                b[nt][0] = __float_as_uint(Gs[kk + tig][d0]);
                b[nt][1] = __float_as_uint(Gs[kk + tig + 4][d0]);
            }
#pragma unroll
            for (int mt = 0; mt < 2; mt++)
#pragma unroll
                for (int nt = 0; nt < 2; nt++) mma8(acc[mt][nt], a[mt], b[nt]);
        }
#pragma unroll
        for (int mt = 0; mt < 2; mt++)
#pragma unroll
            for (int nt = 0; nt < 2; nt++) {
                int f0 = wm * 32 + mt * 16 + g;
                int d = dt * 64 + wn * 16 + nt * 8 + 2 * tig;
#pragma unroll
                for (int h2 = 0; h2 < 2; h2++) {
                    float2 o = make_float2(acc[mt][nt][h2 * 2], acc[mt][nt][h2 * 2 + 1]);
                    *reinterpret_cast<float2*>(&dS[((size_t)bc * 64 + f0 + h2 * 8) * 256 + d]) = o;
                }
            }
    }
}

// ---------------- exclusive prefix of chunk states -------------------------
__global__ void state_prefix_k(float* __restrict__ dS)
{
    int idx = blockIdx.x * blockDim.x + threadIdx.x;
    int b = idx / (64 * 256);
    int fd = idx % (64 * 256);
    float carry = 0.f;
    for (int c = 0; c < NCc; c++) {
        size_t o = ((size_t)(b * NCc + c)) * 64 * 256 + fd;
        float v = dS[o];
        dS[o] = carry;
        carry += v;
    }
}

// ---------------- kv pass3 (fp32 for now) ----------------------------------
__global__ __launch_bounds__(256) void kv_pass3_k(const float* __restrict__ Kq,
                                                  const float* __restrict__ U,
                                                  const float* __restrict__ GV,
                                                  const float* __restrict__ Spre,
                                                  const float* __restrict__ gcum,
                                                  float* __restrict__ comb)
{
    __shared__ float Ks[64][65];
    __shared__ float SU[64][65];
    __shared__ float Bs[64][33];
    int bc = blockIdx.x;
    size_t rowbase = (size_t)bc * 64;
    int tid = threadIdx.x;
#pragma unroll
    for (int i = 0; i < 16; i++) {
        int idx = tid + i * 256; int t = idx >> 6, f = idx & 63;
        Ks[t][f] = Kq[(rowbase + t) * 64 + f];
        SU[t][f] = U[(rowbase + t) * 64 + f];
    }
    __syncthreads();
    float sl[16];
#pragma unroll
    for (int i = 0; i < 16; i++) {
        int idx = tid + i * 256; int l = idx >> 6, t = idx & 63;
        float s = 0.f;
        if (t <= l) {
#pragma unroll
            for (int f = 0; f < 64; f++) s += Ks[l][f] * SU[t][f];
        }
        sl[i] = s;
    }
    __syncthreads();
#pragma unroll
    for (int i = 0; i < 16; i++) {
        int idx = tid + i * 256; int l = idx >> 6, t = idx & 63;
        SU[l][t] = sl[i];
    }
    __syncthreads();
    int tRow = tid >> 4, tCol = tid & 15;
    int l0 = tRow * 4;
    float scl[4];
#pragma unroll
    for (int i = 0; i < 4; i++) {
        float gc = gcum[rowbase + l0 + i];
        scl[i] = rsqrtf(fmaxf(gc, 1.0f)) * INV_SQRT_P;
    }
    for (int dt = 0; dt < 8; dt++) {
        int d0 = dt * 32;
#pragma unroll
        for (int i = 0; i < 8; i++) {
            int idx = tid + i * 256; int t = idx >> 5, d = idx & 31;
            Bs[t][d] = GV[(rowbase + t) * 256 + d0 + d];
        }
        __syncthreads();
        float acc[4][2] = {};
        for (int t = 0; t < 64; t++) {
            float b0 = Bs[t][tCol * 2], b1 = Bs[t][tCol * 2 + 1];
#pragma unroll
            for (int i = 0; i < 4; i++) {
                float s = SU[l0 + i][t];
                acc[i][0] += s * b0;
                acc[i][1] += s * b1;
            }
        }
        __syncthreads();
#pragma unroll
        for (int i = 0; i < 8; i++) {
            int idx = tid + i * 256; int f = idx >> 5, d = idx & 31;
            Bs[f][d] = Spre[((size_t)bc * 64 + f) * 256 + d0 + d];
        }
        __syncthreads();
        for (int f = 0; f < 64; f++) {
            float b0 = Bs[f][tCol * 2], b1 = Bs[f][tCol * 2 + 1];
#pragma unroll
            for (int i = 0; i < 4; i++) {
                float k = Ks[l0 + i][f];
                acc[i][0] += k * b0;
                acc[i][1] += k * b1;
            }
        }
        __syncthreads();
#pragma unroll
        for (int i = 0; i < 4; i++)
#pragma unroll
            for (int j = 0; j < 2; j++) {
                size_t o = (rowbase + l0 + i) * 256 + d0 + tCol * 2 + j;
                comb[o] += acc[i][j] * scl[i];
            }
    }
}

// ---------------- layernorm -------------------------------------------------
__global__ __launch_bounds__(256) void ln_k(const float* __restrict__ c,
                                            const float* __restrict__ g,
                                            const float* __restrict__ bt,
                                            float* __restrict__ out)
{
    int m = blockIdx.x, t = threadIdx.x;
    float v = c[(size_t)m * 256 + t];
    float s = v, s2 = v * v;
#pragma unroll
    for (int o = 16; o; o >>= 1) {
        s += __shfl_xor_sync(0xffffffffu, s, o);
        s2 += __shfl_xor_sync(0xffffffffu, s2, o);
    }
    __shared__ float ws[8], ws2[8];
    int w = t >> 5, lane = t & 31;
    if (lane == 0) { ws[w] = s; ws2[w] = s2; }
    __syncthreads();
    if (w == 0) {
        s = (lane < 8) ? ws[lane] : 0.f;
        s2 = (lane < 8) ? ws2[lane] : 0.f;
#pragma unroll
        for (int o = 4; o; o >>= 1) {
            s += __shfl_xor_sync(0xffffffffu, s, o);
            s2 += __shfl_xor_sync(0xffffffffu, s2, o);
        }
        if (lane == 0) { ws[0] = s; ws2[0] = s2; }
    }
    __syncthreads();
    float mean = ws[0] * (1.0f / 256.0f);
    float var = ws2[0] * (1.0f / 256.0f) - mean * mean;
    out[(size_t)m * 256 + t] = (v - mean) * rsqrtf(var + 1e-5f) * g[t] + bt[t];
}

// ---------------- host launch -----------------------------------------------
extern "C" void kernel_launch(void* const* d_in, const int* in_sizes, int n_in,
                              void* d_out, int out_size)
{
    (void)in_sizes; (void)n_in; (void)out_size;
    const float* x        = (const float*)d_in[0];
    const float* pos_ph   = (const float*)d_in[1];
    const float* w_mem1v  = (const float*)d_in[2];
    const float* b_mem1v  = (const float*)d_in[3];
    const float* w_mem1o  = (const float*)d_in[4];
    const float* b_mem1o  = (const float*)d_in[5];
    const float* w_off    = (const float*)d_in[6];
    const float* b_off    = (const float*)d_in[7];
    const float* w_key    = (const float*)d_in[8];
    const float* b_key    = (const float*)d_in[9];
    const float* w_val    = (const float*)d_in[10];
    const float* b_val    = (const float*)d_in[11];
    const float* w_sk1    = (const float*)d_in[12];
    const float* b_sk1    = (const float*)d_in[13];
    const float* w_sk2    = (const float*)d_in[14];
    const float* b_sk2    = (const float*)d_in[15];
    const float* w_gate   = (const float*)d_in[16];
    const float* b_gate   = (const float*)d_in[17];
    const float* ln_g     = (const float*)d_in[18];
    const float* ln_b     = (const float*)d_in[19];
    const float* w_out    = (const float*)d_in[20];
    const float* b_out    = (const float*)d_in[21];
    float* out = (float*)d_out;

    float* buf = nullptr;
    cudaGetSymbolAddress((void**)&buf, g_buf);
    float* v1    = buf + OFF_V1;
    float* offp  = buf + OFF_OFFP;
    float* pcon  = buf + OFF_PCON;
    float* pc    = buf + OFF_PC;
    float* ps    = buf + OFF_PS;
    float* ac    = buf + OFF_AC;
    float* pr    = buf + OFF_POSRET;
    float* kq    = buf + OFF_KQ;
    float* u     = buf + OFF_U;
    float* gate  = buf + OFF_GATE;
    float* gcum  = buf + OFF_GCUM;
    float* gv    = buf + OFF_GV;
    float* xcat  = buf + OFF_XCAT;
    float* h     = buf + OFF_H;
    float* csum  = buf + OFF_CSUM;
    float* dS    = buf + OFF_DS;
    float* comb  = buf + OFF_COMB;
    float* lnb   = buf + OFF_LN;

    dim3 gS(1, Mc / 64);      // skinny N=32 GEMMs: BM=64, BN=32
    dim3 gW(4, Mc / 128);     // wide N=256 GEMMs: BM=128, BN=64

    // pos tables + pos part of offset
    pos_pre_k<<<(Lc * Pc) / 256, 256>>>(pos_ph, w_off, b_off, pc, ps, pcon);
    // v1 = x@w_mem1v + b
    tgemm_k<64, 32, 1, 2, 0, 0><<<gS, 256>>>(x, w_mem1v, b_mem1v, nullptr, nullptr, v1, Pc, Dc);
    // offset = tanh(x@w_off[:D] + pcon)*pi    (split for phase accuracy)
    tgemm_k<64, 32, 1, 2, 1, 1><<<gS, 256>>>(x, w_off, nullptr, pcon, nullptr, offp, Pc, Dc);
    // mem1 cumsums
    pack_ac_k<<<(Mc * Pc) / 256, 256>>>(v1, pc, ps, ac);
    scan_chunk_sums_k<<<Bc * NCc, 64>>>(ac, csum, 64, 64);
    scan_prefix_k<<<Bc, 64>>>(csum, 64);
    scan_apply_k<<<Bc * NCc, 64>>>(ac, csum, ac, 64, 64, 64);
    posret_k<<<(Mc * Pc) / 256, 256>>>(offp, pc, ps, ac, pr);
    // comb = pos_ret @ w_mem1o + b
    tgemm_k<128, 64, 2, 4, 0, 0><<<gW, 256>>>(pr, w_mem1o, b_mem1o, nullptr, nullptr, comb, Dc, Pc);
    // key phases -> kq (trig fused, split)
    tgemm_k<64, 32, 1, 2, 3, 1><<<gS, 256>>>(x, w_key, b_key, nullptr, nullptr, kq, Pc, Dc);
    // gate, then gv = (x@w_val + b)*gate fused
    gate_k<<<Mc / 8, 256>>>(x, w_gate, b_gate, gate);
    tgemm_k<128, 64, 2, 4, 4, 0><<<gW, 256>>>(x, w_val, b_val, gate, nullptr, gv, Dc, Dc);
    gate_scan_k<<<Bc, 32>>>(gate, gcum);
    // context avg -> xcat
    scan_chunk_sums_k<<<Bc * NCc, 256>>>(x, csum, 256, 256);
    scan_prefix_k<<<Bc, 256>>>(csum, 256);
    scan_apply_k<<<Bc * NCc, 256>>>(x, csum, xcat + 256, 256, 256, 512);
    xcat_fill_k<<<(Mc * Dc) / 256, 256>>>(x, xcat);
    // h = gelu(xcat@w_sk1 + b)
    tgemm_k<128, 64, 2, 4, 2, 0><<<gW, 256>>>(xcat, w_sk1, b_sk1, nullptr, nullptr, h, Dc, 2 * Dc);
    // storage phases -> u (trig fused, split)
    tgemm_k<64, 32, 1, 2, 3, 1><<<gS, 256>>>(h, w_sk2, b_sk2, nullptr, nullptr, u, Pc, Dc);
    // chunked linear attention
    chunk_delta_k<<<Bc * NCc, 256>>>(u, gv, dS);
    state_prefix_k<<<(Bc * 64 * 256) / 256, 256>>>(dS);
    kv_pass3_k<<<Bc * NCc, 256>>>(kq, u, gv, dS, gcum, comb);
    // layernorm + output projection + residual
    ln_k<<<Mc, 256>>>(comb, ln_g, ln_b, lnb);
    tgemm_k<128, 64, 2, 4, 0, 0><<<gW, 256>>>(lnb, w_out, b_out, nullptr, x, out, Dc, Dc);
}

// round 4
// speedup vs baseline: 2.1167x; 1.3471x over previous
#include <cuda_runtime.h>
#include <cstdint>
#include <math.h>

#define Bc 4
#define Lc 2048
#define Dc 256
#define Pc 32
#define Mc 8192
#define NCc 32
#define CHc 64
#define PIF 3.14159265358979323846f
#define INV_SQRT_P 0.17677669529663688f

// ---------------- scratch (single static device buffer, no allocs) --------
static constexpr size_t OFF_OFFP   = 262144;       // 8192*32
static constexpr size_t OFF_PCON   = 524288;       // 2048*32
static constexpr size_t OFF_PC     = 589824;       // 2048*32
static constexpr size_t OFF_PS     = 655360;       // 2048*32
static constexpr size_t OFF_AC     = 720896;       // 8192*64
static constexpr size_t OFF_POSRET = 1245184;      // 8192*32
static constexpr size_t OFF_KQ     = 1769472;      // 8192*64
static constexpr size_t OFF_U      = 2555904;      // 8192*64
static constexpr size_t OFF_GATE   = 5177344;      // 8192
static constexpr size_t OFF_GCUM   = 5185536;      // 8192
static constexpr size_t OFF_GV     = 5193728;      // 8192*256
static constexpr size_t OFF_XCAT   = 7290880;      // 8192*512
static constexpr size_t OFF_H      = 11485184;     // 8192*256
static constexpr size_t OFF_CSUM   = 13582336;     // 4*32*256
static constexpr size_t OFF_DS     = 13615104;     // 4*32*64*256
static constexpr size_t OFF_COMB   = 15712256;     // 8192*256
static constexpr size_t OFF_LN     = 17809408;     // 8192*256
static constexpr size_t OFF_CSUM2  = 19906560;     // 4*32*64
static constexpr size_t TOTAL_F    = 19914752;

__device__ float g_buf[TOTAL_F];

// ---------------- tf32 mma helpers ----------------------------------------
__device__ __forceinline__ uint32_t f2tf(float f) {
    uint32_t u;
    asm("cvt.rna.tf32.f32 %0, %1;" : "=r"(u) : "f"(f));
    return u;
}

__device__ __forceinline__ void mma8(float* c, const uint32_t* a, const uint32_t* b) {
    asm volatile(
        "mma.sync.aligned.m16n8k8.row.col.f32.tf32.tf32.f32 "
        "{%0,%1,%2,%3},{%4,%5,%6,%7},{%8,%9},{%0,%1,%2,%3};"
        : "+f"(c[0]), "+f"(c[1]), "+f"(c[2]), "+f"(c[3])
        : "r"(a[0]), "r"(a[1]), "r"(a[2]), "r"(a[3]), "r"(b[0]), "r"(b[1]));
}

// ---------------- tensor-core GEMM -----------------------------------------
// ACT: 0 none, 1 tanh*pi, 2 gelu, 3 tanh*pi->cos/sin packed (stride 64),
//      4 (v+bias)*addRow[row] (gate fuse),
//      5 pack-ac: ac[row*64+col]=addRow(pc)[lrow*32+col]*v; +32 with resid(ps)
template<int BM, int BN, int MT, int NT, int ACT, int SPLIT>
__global__ __launch_bounds__(256) void tgemm_k(
    const float* __restrict__ A, const float* __restrict__ W,
    const float* __restrict__ bias, const float* __restrict__ addRow,
    const float* __restrict__ resid, float* __restrict__ C,
    int N, int K)
{
    static_assert(BM == 4 * MT * 16 && BN == 2 * NT * 8, "tile mismatch");
    const int BK = 32;
    __shared__ float As[BM][BK + 4];
    __shared__ float Ws[BK][BN + 8];
    int tid = threadIdx.x;
    int warp = tid >> 5, lane = tid & 31;
    int wm = warp >> 1, wn = warp & 1;
    int g = lane >> 2, tig = lane & 3;
    int bm = blockIdx.y * BM, bn = blockIdx.x * BN;

    float acc[MT][NT][4] = {};

    for (int k0 = 0; k0 < K; k0 += BK) {
        constexpr int AF4 = BM * BK / 4 / 256;
#pragma unroll
        for (int i = 0; i < AF4; i++) {
            int id = tid + 256 * i;
            int r = id >> 3, c4 = (id & 7) << 2;
            float4 v = *reinterpret_cast<const float4*>(A + (size_t)(bm + r) * K + k0 + c4);
            if (!SPLIT) {
                v.x = __uint_as_float(f2tf(v.x)); v.y = __uint_as_float(f2tf(v.y));
                v.z = __uint_as_float(f2tf(v.z)); v.w = __uint_as_float(f2tf(v.w));
            }
            *reinterpret_cast<float4*>(&As[r][c4]) = v;
        }
        constexpr int WF4 = BK * BN / 4 / 256;
#pragma unroll
        for (int i = 0; i < WF4; i++) {
            int id = tid + 256 * i;
            int r = id / (BN / 4), c4 = (id % (BN / 4)) << 2;
            float4 v = *reinterpret_cast<const float4*>(W + (size_t)(k0 + r) * N + bn + c4);
            if (!SPLIT) {
                v.x = __uint_as_float(f2tf(v.x)); v.y = __uint_as_float(f2tf(v.y));
                v.z = __uint_as_float(f2tf(v.z)); v.w = __uint_as_float(f2tf(v.w));
            }
            *reinterpret_cast<float4*>(&Ws[r][c4]) = v;
        }
        __syncthreads();
#pragma unroll
        for (int ks = 0; ks < 4; ks++) {
            int kk = ks * 8;
            uint32_t ah[MT][4], al[MT][4];
#pragma unroll
            for (int mt = 0; mt < MT; mt++) {
                int r0 = wm * MT * 16 + mt * 16 + g;
                float f0 = As[r0][kk + tig],     f1 = As[r0 + 8][kk + tig];
                float f2 = As[r0][kk + tig + 4], f3 = As[r0 + 8][kk + tig + 4];
                if (SPLIT) {
                    ah[mt][0] = f2tf(f0); al[mt][0] = f2tf(f0 - __uint_as_float(ah[mt][0]));
                    ah[mt][1] = f2tf(f1); al[mt][1] = f2tf(f1 - __uint_as_float(ah[mt][1]));
                    ah[mt][2] = f2tf(f2); al[mt][2] = f2tf(f2 - __uint_as_float(ah[mt][2]));
                    ah[mt][3] = f2tf(f3); al[mt][3] = f2tf(f3 - __uint_as_float(ah[mt][3]));
                } else {
                    ah[mt][0] = __float_as_uint(f0); ah[mt][1] = __float_as_uint(f1);
                    ah[mt][2] = __float_as_uint(f2); ah[mt][3] = __float_as_uint(f3);
                }
            }
            uint32_t bh[NT][2], bl[NT][2];
#pragma unroll
            for (int nt = 0; nt < NT; nt++) {
                int cn = wn * NT * 8 + nt * 8 + g;
                float f0 = Ws[kk + tig][cn], f1 = Ws[kk + tig + 4][cn];
                if (SPLIT) {
                    bh[nt][0] = f2tf(f0); bl[nt][0] = f2tf(f0 - __uint_as_float(bh[nt][0]));
                    bh[nt][1] = f2tf(f1); bl[nt][1] = f2tf(f1 - __uint_as_float(bh[nt][1]));
                } else {
                    bh[nt][0] = __float_as_uint(f0); bh[nt][1] = __float_as_uint(f1);
                }
            }
#pragma unroll
            for (int mt = 0; mt < MT; mt++)
#pragma unroll
                for (int nt = 0; nt < NT; nt++) {
                    mma8(acc[mt][nt], ah[mt], bh[nt]);
                    if (SPLIT) {
                        mma8(acc[mt][nt], al[mt], bh[nt]);
                        mma8(acc[mt][nt], ah[mt], bl[nt]);
                    }
                }
        }
        __syncthreads();
    }

#pragma unroll
    for (int mt = 0; mt < MT; mt++)
#pragma unroll
        for (int nt = 0; nt < NT; nt++) {
            int r0 = bm + wm * MT * 16 + mt * 16 + g;
            int col = bn + wn * NT * 8 + nt * 8 + 2 * tig;
#pragma unroll
            for (int h2 = 0; h2 < 2; h2++) {
                int row = r0 + h2 * 8;
                int lrow = row & (Lc - 1);
                float v0 = acc[mt][nt][h2 * 2 + 0];
                float v1 = acc[mt][nt][h2 * 2 + 1];
                if (bias) { v0 += bias[col]; v1 += bias[col + 1]; }
                if (ACT == 4) {
                    float gt = addRow[row];
                    v0 *= gt; v1 *= gt;
                } else if (ACT != 5 && addRow) {
                    v0 += addRow[(size_t)lrow * N + col];
                    v1 += addRow[(size_t)lrow * N + col + 1];
                }
                if (ACT == 1) { v0 = tanhf(v0) * PIF; v1 = tanhf(v1) * PIF; }
                else if (ACT == 2) {
                    v0 = 0.5f * v0 * (1.0f + erff(v0 * 0.70710678118654752f));
                    v1 = 0.5f * v1 * (1.0f + erff(v1 * 0.70710678118654752f));
                }
                if (ACT == 3) {
                    v0 = tanhf(v0) * PIF; v1 = tanhf(v1) * PIF;
                    C[(size_t)row * 64 + col]          = cosf(v0);
                    C[(size_t)row * 64 + 32 + col]     = sinf(v0);
                    C[(size_t)row * 64 + col + 1]      = cosf(v1);
                    C[(size_t)row * 64 + 32 + col + 1] = sinf(v1);
                } else if (ACT == 5) {
                    float pc0 = addRow[(size_t)lrow * 32 + col];
                    float pc1 = addRow[(size_t)lrow * 32 + col + 1];
                    float ps0 = resid[(size_t)lrow * 32 + col];
                    float ps1 = resid[(size_t)lrow * 32 + col + 1];
                    C[(size_t)row * 64 + col]          = pc0 * v0;
                    C[(size_t)row * 64 + 32 + col]     = ps0 * v0;
                    C[(size_t)row * 64 + col + 1]      = pc1 * v1;
                    C[(size_t)row * 64 + 32 + col + 1] = ps1 * v1;
                } else {
                    if (resid) {
                        v0 += resid[(size_t)row * N + col];
                        v1 += resid[(size_t)row * N + col + 1];
                    }
                    float2 o = make_float2(v0, v1);
                    *reinterpret_cast<float2*>(&C[(size_t)row * N + col]) = o;
                }
            }
        }
}

// ---------------- pos precompute -------------------------------------------
__global__ void pos_pre_k(const float* __restrict__ ph, const float* __restrict__ w_off,
                          const float* __restrict__ b_off,
                          float* __restrict__ pc, float* __restrict__ ps,
                          float* __restrict__ pcon)
{
    int idx = blockIdx.x * blockDim.x + threadIdx.x;
    if (idx >= Lc * Pc) return;
    int l = idx >> 5, p = idx & 31;
    float s = b_off[p];
#pragma unroll
    for (int q = 0; q < Pc; q++) s += ph[l * Pc + q] * w_off[(Dc + q) * Pc + p];
    pcon[idx] = s;
    float v = ph[idx];
    pc[idx] = cosf(v);
    ps[idx] = sinf(v);
}

// ---------------- small kernels --------------------------------------------
__global__ void xcat_fill_k(const float* __restrict__ x, float* __restrict__ xc)
{
    int idx = blockIdx.x * blockDim.x + threadIdx.x;
    int m = idx >> 8, d = idx & 255, l = m & (Lc - 1);
    xc[(size_t)m * 512 + d] = x[idx];
    xc[(size_t)m * 512 + 256 + d] *= 1.0f / (float)(l + 1);
}

__global__ void gate_k(const float* __restrict__ x, const float* __restrict__ w,
                       const float* __restrict__ b, float* __restrict__ gate)
{
    int warp = (blockIdx.x * blockDim.x + threadIdx.x) >> 5;
    int lane = threadIdx.x & 31;
    if (warp >= Mc) return;
    const float* xr = x + (size_t)warp * Dc;
    float s = 0.f;
#pragma unroll
    for (int i = 0; i < Dc / 32; i++) s += xr[lane + 32 * i] * w[lane + 32 * i];
#pragma unroll
    for (int o = 16; o; o >>= 1) s += __shfl_xor_sync(0xffffffffu, s, o);
    if (lane == 0) gate[warp] = 1.0f / (1.0f + expf(-(s + b[0])));
}

// ---------------- chunked scans --------------------------------------------
__global__ void scan_chunk_sums_k(const float* __restrict__ in, float* __restrict__ csum,
                                  int F, int inStride)
{
    int bc = blockIdx.x, b = bc / NCc, c = bc % NCc, f = threadIdx.x;
    const float* p = in + ((size_t)b * Lc + c * CHc) * inStride + f;
    float s = 0.f;
    for (int i = 0; i < CHc; i++) s += p[(size_t)i * inStride];
    csum[(size_t)bc * F + f] = s;
}

__global__ void scan_prefix_k(float* __restrict__ csum, int F)
{
    int b = blockIdx.x, f = threadIdx.x;
    float carry = 0.f;
    for (int c = 0; c < NCc; c++) {
        size_t idx = ((size_t)b * NCc + c) * F + f;
        float v = csum[idx];
        csum[idx] = carry;
        carry += v;
    }
}

__global__ void scan_apply_k(const float* __restrict__ in, const float* __restrict__ csum,
                             float* __restrict__ out, int F, int inStride, int outStride)
{
    int bc = blockIdx.x, b = bc / NCc, c = bc % NCc, f = threadIdx.x;
    float carry = csum[(size_t)bc * F + f];
    const float* p = in + ((size_t)b * Lc + c * CHc) * inStride + f;
    float* q = out + ((size_t)b * Lc + c * CHc) * outStride + f;
    for (int i = 0; i < CHc; i++) {
        carry += p[(size_t)i * inStride];
        q[(size_t)i * outStride] = carry;
    }
}

// fused: cumsum of ac over this chunk (to shared) + posret epilogue
__global__ __launch_bounds__(64) void scan_apply_posret_k(
    const float* __restrict__ ac, const float* __restrict__ csum,
    const float* __restrict__ offp, const float* __restrict__ pc,
    const float* __restrict__ ps, float* __restrict__ pr)
{
    __shared__ float sh[64][65];
    int bc = blockIdx.x, f = threadIdx.x;
    size_t rowbase = (size_t)bc * 64;
    float carry = csum[(size_t)bc * 64 + f];
    const float* p = ac + rowbase * 64 + f;
    for (int i = 0; i < CHc; i++) {
        carry += p[(size_t)i * 64];
        sh[i][f] = carry;
    }
    __syncthreads();
#pragma unroll
    for (int j = 0; j < 32; j++) {
        int idx = j * 64 + f;
        int i = idx >> 5, pp = idx & 31;
        size_t m = rowbase + i;
        int l = (int)(m & (Lc - 1));
        float o = offp[m * 32 + pp];
        float oc = cosf(o), os = sinf(o);
        float pcv = pc[l * 32 + pp], psv = ps[l * 32 + pp];
        float qc = pcv * oc - psv * os;
        float qs = psv * oc + pcv * os;
        pr[m * 32 + pp] = (sh[i][pp] * qc + sh[i][32 + pp] * qs) * INV_SQRT_P;
    }
}

__global__ void gate_scan_k(const float* __restrict__ g, float* __restrict__ gc)
{
    int b = blockIdx.x, t = threadIdx.x;
    const float* p = g + b * Lc + t * CHc;
    float s = 0.f;
    for (int i = 0; i < CHc; i++) s += p[i];
    float xv = s;
#pragma unroll
    for (int o = 1; o < 32; o <<= 1) {
        float v = __shfl_up_sync(0xffffffffu, xv, o);
        if (t >= o) xv += v;
    }
    float carry = xv - s;
    float* q = gc + b * Lc + t * CHc;
    for (int i = 0; i < CHc; i++) { carry += p[i]; q[i] = carry; }
}

// ---------------- chunk state delta via tf32 mma ---------------------------
__global__ __launch_bounds__(256) void chunk_delta_k(const float* __restrict__ U,
                                                     const float* __restrict__ GV,
                                                     float* __restrict__ dS)
{
    __shared__ float Us[64][72];
    __shared__ float Gs[64][72];
    int bc = blockIdx.x;
    size_t rowbase = (size_t)bc * 64;
    int tid = threadIdx.x;
    int warp = tid >> 5, lane = tid & 31;
    int wm = warp >> 2, wn = warp & 3;
    int g = lane >> 2, tig = lane & 3;

#pragma unroll
    for (int i = 0; i < 4; i++) {
        int id = tid + 256 * i;
        int t = id >> 4, f = (id & 15) << 2;
        float4 v = *reinterpret_cast<const float4*>(U + (rowbase + t) * 64 + f);
        v.x = __uint_as_float(f2tf(v.x)); v.y = __uint_as_float(f2tf(v.y));
        v.z = __uint_as_float(f2tf(v.z)); v.w = __uint_as_float(f2tf(v.w));
        *reinterpret_cast<float4*>(&Us[t][f]) = v;
    }

    for (int dt = 0; dt < 4; dt++) {
        __syncthreads();
#pragma unroll
        for (int i = 0; i < 4; i++) {
            int id = tid + 256 * i;
            int t = id >> 4, d = (id & 15) << 2;
            float4 v = *reinterpret_cast<const float4*>(GV + (rowbase + t) * 256 + dt * 64 + d);
            v.x = __uint_as_float(f2tf(v.x)); v.y = __uint_as_float(f2tf(v.y));
            v.z = __uint_as_float(f2tf(v.z)); v.w = __uint_as_float(f2tf(v.w));
            *reinterpret_cast<float4*>(&Gs[t][d]) = v;
        }
        __syncthreads();

        float acc[2][2][4] = {};
#pragma unroll
        for (int ks = 0; ks < 8; ks++) {
            int kk = ks * 8;
            uint32_t a[2][4], b[2][2];
#pragma unroll
            for (int mt = 0; mt < 2; mt++) {
                int f0 = wm * 32 + mt * 16 + g;
                a[mt][0] = __float_as_uint(Us[kk + tig][f0]);
                a[mt][1] = __float_as_uint(Us[kk + tig][f0 + 8]);
                a[mt][2] = __float_as_uint(Us[kk + tig + 4][f0]);
                a[mt][3] = __float_as_uint(Us[kk + tig + 4][f0 + 8]);
            }
#pragma unroll
            for (int nt = 0; nt < 2; nt++) {
                int d0 = wn * 16 + nt * 8 + g;
                b[nt][0] = __float_as_uint(Gs[kk + tig][d0]);
                b[nt][1] = __float_as_uint(Gs[kk + tig + 4][d0]);
            }
#pragma unroll
            for (int mt = 0; mt < 2; mt++)
#pragma unroll
                for (int nt = 0; nt < 2; nt++) mma8(acc[mt][nt], a[mt], b[nt]);
        }
#pragma unroll
        for (int mt = 0; mt < 2; mt++)
#pragma unroll
            for (int nt = 0; nt < 2; nt++) {
                int f0 = wm * 32 + mt * 16 + g;
                int d = dt * 64 + wn * 16 + nt * 8 + 2 * tig;
#pragma unroll
                for (int h2 = 0; h2 < 2; h2++) {
                    float2 o = make_float2(acc[mt][nt][h2 * 2], acc[mt][nt][h2 * 2 + 1]);
                    *reinterpret_cast<float2*>(&dS[((size_t)bc * 64 + f0 + h2 * 8) * 256 + d]) = o;
                }
            }
    }
}

// ---------------- exclusive prefix of chunk states -------------------------
__global__ void state_prefix_k(float* __restrict__ dS)
{
    int idx = blockIdx.x * blockDim.x + threadIdx.x;
    int b = idx / (64 * 256);
    int fd = idx % (64 * 256);
    float carry = 0.f;
    for (int c = 0; c < NCc; c++) {
        size_t o = ((size_t)(b * NCc + c)) * 64 * 256 + fd;
        float v = dS[o];
        dS[o] = carry;
        carry += v;
    }
}

// ---------------- kv pass3 + fused layernorm -------------------------------
__global__ __launch_bounds__(256) void kv_pass3_ln_k(
    const float* __restrict__ Kq, const float* __restrict__ U,
    const float* __restrict__ GV, const float* __restrict__ Spre,
    const float* __restrict__ gcum, const float* __restrict__ comb,
    const float* __restrict__ lng, const float* __restrict__ lnbv,
    float* __restrict__ outb)
{
    __shared__ float Ks[64][65];
    __shared__ float SU[64][65];
    __shared__ float Bs[64][33];
    int bc = blockIdx.x;
    size_t rowbase = (size_t)bc * 64;
    int tid = threadIdx.x;
#pragma unroll
    for (int i = 0; i < 16; i++) {
        int idx = tid + i * 256; int t = idx >> 6, f = idx & 63;
        Ks[t][f] = Kq[(rowbase + t) * 64 + f];
        SU[t][f] = U[(rowbase + t) * 64 + f];
    }
    __syncthreads();
    float sl[16];
#pragma unroll
    for (int i = 0; i < 16; i++) {
        int idx = tid + i * 256; int l = idx >> 6, t = idx & 63;
        float s = 0.f;
        if (t <= l) {
#pragma unroll
            for (int f = 0; f < 64; f++) s += Ks[l][f] * SU[t][f];
        }
        sl[i] = s;
    }
    __syncthreads();
#pragma unroll
    for (int i = 0; i < 16; i++) {
        int idx = tid + i * 256; int l = idx >> 6, t = idx & 63;
        SU[l][t] = sl[i];
    }
    __syncthreads();
    int tRow = tid >> 4, tCol = tid & 15;
    int l0 = tRow * 4;
    float scl[4];
#pragma unroll
    for (int i = 0; i < 4; i++) {
        float gc = gcum[rowbase + l0 + i];
        scl[i] = rsqrtf(fmaxf(gc, 1.0f)) * INV_SQRT_P;
    }
    float r[4][16];
    for (int dt = 0; dt < 8; dt++) {
        int d0 = dt * 32;
#pragma unroll
        for (int i = 0; i < 8; i++) {
            int idx = tid + i * 256; int t = idx >> 5, d = idx & 31;
            Bs[t][d] = GV[(rowbase + t) * 256 + d0 + d];
        }
        __syncthreads();
        float acc[4][2] = {};
        for (int t = 0; t < 64; t++) {
            float b0 = Bs[t][tCol * 2], b1 = Bs[t][tCol * 2 + 1];
#pragma unroll
            for (int i = 0; i < 4; i++) {
                float s = SU[l0 + i][t];
                acc[i][0] += s * b0;
                acc[i][1] += s * b1;
            }
        }
        __syncthreads();
#pragma unroll
        for (int i = 0; i < 8; i++) {
            int idx = tid + i * 256; int f = idx >> 5, d = idx & 31;
            Bs[f][d] = Spre[((size_t)bc * 64 + f) * 256 + d0 + d];
        }
        __syncthreads();
        for (int f = 0; f < 64; f++) {
            float b0 = Bs[f][tCol * 2], b1 = Bs[f][tCol * 2 + 1];
#pragma unroll
            for (int i = 0; i < 4; i++) {
                float k = Ks[l0 + i][f];
                acc[i][0] += k * b0;
                acc[i][1] += k * b1;
            }
        }
        __syncthreads();
#pragma unroll
        for (int i = 0; i < 4; i++)
#pragma unroll
            for (int j = 0; j < 2; j++) {
                size_t o = (rowbase + l0 + i) * 256 + d0 + tCol * 2 + j;
                r[i][dt * 2 + j] = comb[o] + acc[i][j] * scl[i];
            }
    }
    // fused layernorm over the 64 rows this block fully owns
    float s[4] = {}, s2[4] = {};
#pragma unroll
    for (int i = 0; i < 4; i++)
#pragma unroll
        for (int j = 0; j < 16; j++) { s[i] += r[i][j]; s2[i] += r[i][j] * r[i][j]; }
#pragma unroll
    for (int o = 1; o <= 8; o <<= 1) {
#pragma unroll
        for (int i = 0; i < 4; i++) {
            s[i]  += __shfl_xor_sync(0xffffffffu, s[i],  o);
            s2[i] += __shfl_xor_sync(0xffffffffu, s2[i], o);
        }
    }
    float mean[4], rstd[4];
#pragma unroll
    for (int i = 0; i < 4; i++) {
        mean[i] = s[i] * (1.0f / 256.0f);
        float var = s2[i] * (1.0f / 256.0f) - mean[i] * mean[i];
        rstd[i] = rsqrtf(var + 1e-5f);
    }
#pragma unroll
    for (int dt = 0; dt < 8; dt++) {
        int col = dt * 32 + tCol * 2;
        float g0 = lng[col], g1 = lng[col + 1];
        float b0 = lnbv[col], b1 = lnbv[col + 1];
#pragma unroll
        for (int i = 0; i < 4; i++) {
            float v0 = (r[i][dt * 2]     - mean[i]) * rstd[i] * g0 + b0;
            float v1 = (r[i][dt * 2 + 1] - mean[i]) * rstd[i] * g1 + b1;
            *reinterpret_cast<float2*>(&outb[(rowbase + l0 + i) * 256 + col]) =
                make_float2(v0, v1);
        }
    }
}

// ---------------- stream/event context (created once, outside capture) -----
namespace {
struct Ctx {
    cudaStream_t s1, s2;
    cudaEvent_t eR1, eR2, eGV, eA, eBC;
    Ctx() {
        cudaStreamCreateWithFlags(&s1, cudaStreamNonBlocking);
        cudaStreamCreateWithFlags(&s2, cudaStreamNonBlocking);
        cudaEventCreateWithFlags(&eR1, cudaEventDisableTiming);
        cudaEventCreateWithFlags(&eR2, cudaEventDisableTiming);
        cudaEventCreateWithFlags(&eGV, cudaEventDisableTiming);
        cudaEventCreateWithFlags(&eA, cudaEventDisableTiming);
        cudaEventCreateWithFlags(&eBC, cudaEventDisableTiming);
    }
};
Ctx& C() { static Ctx c; return c; }
}

// ---------------- host launch -----------------------------------------------
extern "C" void kernel_launch(void* const* d_in, const int* in_sizes, int n_in,
                              void* d_out, int out_size)
{
    (void)in_sizes; (void)n_in; (void)out_size;
    const float* x        = (const float*)d_in[0];
    const float* pos_ph   = (const float*)d_in[1];
    const float* w_mem1v  = (const float*)d_in[2];
    const float* b_mem1v  = (const float*)d_in[3];
    const float* w_mem1o  = (const float*)d_in[4];
    const float* b_mem1o  = (const float*)d_in[5];
    const float* w_off    = (const float*)d_in[6];
    const float* b_off    = (const float*)d_in[7];
    const float* w_key    = (const float*)d_in[8];
    const float* b_key    = (const float*)d_in[9];
    const float* w_val    = (const float*)d_in[10];
    const float* b_val    = (const float*)d_in[11];
    const float* w_sk1    = (const float*)d_in[12];
    const float* b_sk1    = (const float*)d_in[13];
    const float* w_sk2    = (const float*)d_in[14];
    const float* b_sk2    = (const float*)d_in[15];
    const float* w_gate   = (const float*)d_in[16];
    const float* b_gate   = (const float*)d_in[17];
    const float* ln_g     = (const float*)d_in[18];
    const float* ln_b     = (const float*)d_in[19];
    const float* w_out    = (const float*)d_in[20];
    const float* b_out    = (const float*)d_in[21];
    float* out = (float*)d_out;

    float* buf = nullptr;
    cudaGetSymbolAddress((void**)&buf, g_buf);
    float* offp  = buf + OFF_OFFP;
    float* pcon  = buf + OFF_PCON;
    float* pc    = buf + OFF_PC;
    float* ps    = buf + OFF_PS;
    float* ac    = buf + OFF_AC;
    float* pr    = buf + OFF_POSRET;
    float* kq    = buf + OFF_KQ;
    float* u     = buf + OFF_U;
    float* gate  = buf + OFF_GATE;
    float* gcum  = buf + OFF_GCUM;
    float* gv    = buf + OFF_GV;
    float* xcat  = buf + OFF_XCAT;
    float* h     = buf + OFF_H;
    float* csum  = buf + OFF_CSUM;
    float* csum2 = buf + OFF_CSUM2;
    float* dS    = buf + OFF_DS;
    float* comb  = buf + OFF_COMB;
    float* lnb   = buf + OFF_LN;

    Ctx& c = C();
    dim3 gS(1, Mc / 64);
    dim3 gW(4, Mc / 128);

    // fork
    cudaEventRecord(c.eR1, 0);
    cudaStreamWaitEvent(c.s1, c.eR1, 0);
    cudaEventRecord(c.eR2, 0);
    cudaStreamWaitEvent(c.s2, c.eR2, 0);

    // ---- path A (s1): mem1 ----
    pos_pre_k<<<(Lc * Pc) / 256, 256, 0, c.s1>>>(pos_ph, w_off, b_off, pc, ps, pcon);
    tgemm_k<64, 32, 1, 2, 5, 0><<<gS, 256, 0, c.s1>>>(x, w_mem1v, b_mem1v, pc, ps, ac, Pc, Dc);
    tgemm_k<64, 32, 1, 2, 1, 1><<<gS, 256, 0, c.s1>>>(x, w_off, nullptr, pcon, nullptr, offp, Pc, Dc);
    scan_chunk_sums_k<<<Bc * NCc, 64, 0, c.s1>>>(ac, csum2, 64, 64);
    scan_prefix_k<<<Bc, 64, 0, c.s1>>>(csum2, 64);
    scan_apply_posret_k<<<Bc * NCc, 64, 0, c.s1>>>(ac, csum2, offp, pc, ps, pr);
    tgemm_k<128, 64, 2, 4, 0, 0><<<gW, 256, 0, c.s1>>>(pr, w_mem1o, b_mem1o, nullptr, nullptr, comb, Dc, Pc);
    cudaEventRecord(c.eA, c.s1);

    // ---- path B/C (s2): gate, values, keys ----
    gate_k<<<Mc / 8, 256, 0, c.s2>>>(x, w_gate, b_gate, gate);
    tgemm_k<128, 64, 2, 4, 4, 0><<<gW, 256, 0, c.s2>>>(x, w_val, b_val, gate, nullptr, gv, Dc, Dc);
    cudaEventRecord(c.eGV, c.s2);
    gate_scan_k<<<Bc, 32, 0, c.s2>>>(gate, gcum);
    tgemm_k<64, 32, 1, 2, 3, 1><<<gS, 256, 0, c.s2>>>(x, w_key, b_key, nullptr, nullptr, kq, Pc, Dc);
    cudaEventRecord(c.eBC, c.s2);

    // ---- path D (default): storage phases + attention ----
    scan_chunk_sums_k<<<Bc * NCc, 256>>>(x, csum, 256, 256);
    scan_prefix_k<<<Bc, 256>>>(csum, 256);
    scan_apply_k<<<Bc * NCc, 256>>>(x, csum, xcat + 256, 256, 256, 512);
    xcat_fill_k<<<(Mc * Dc) / 256, 256>>>(x, xcat);
    tgemm_k<128, 64, 2, 4, 2, 0><<<gW, 256>>>(xcat, w_sk1, b_sk1, nullptr, nullptr, h, Dc, 2 * Dc);
    tgemm_k<64, 32, 1, 2, 3, 1><<<gS, 256>>>(h, w_sk2, b_sk2, nullptr, nullptr, u, Pc, Dc);
    cudaStreamWaitEvent(0, c.eGV, 0);
    chunk_delta_k<<<Bc * NCc, 256>>>(u, gv, dS);
    state_prefix_k<<<(Bc * 64 * 256) / 256, 256>>>(dS);
    cudaStreamWaitEvent(0, c.eA, 0);
    cudaStreamWaitEvent(0, c.eBC, 0);
    kv_pass3_ln_k<<<Bc * NCc, 256>>>(kq, u, gv, dS, gcum, comb, ln_g, ln_b, lnb);
    tgemm_k<128, 64, 2, 4, 0, 0><<<gW, 256>>>(lnb, w_out, b_out, nullptr, x, out, Dc, Dc);
}

// round 5
// speedup vs baseline: 2.5717x; 1.2150x over previous
#include <cuda_runtime.h>
#include <cstdint>
#include <math.h>

#define Bc 4
#define Lc 2048
#define Dc 256
#define Pc 32
#define Mc 8192
#define NCc 32
#define CHc 64
#define PIF 3.14159265358979323846f
#define INV_SQRT_P 0.17677669529663688f

// ---------------- scratch (single static device buffer, no allocs) --------
static constexpr size_t OFF_OFFP   = 262144;       // 8192*32
static constexpr size_t OFF_PCON   = 524288;       // 2048*32
static constexpr size_t OFF_PC     = 589824;       // 2048*32
static constexpr size_t OFF_PS     = 655360;       // 2048*32
static constexpr size_t OFF_AC     = 720896;       // 8192*64
static constexpr size_t OFF_POSRET = 1245184;      // 8192*32
static constexpr size_t OFF_KQ     = 1769472;      // 8192*64
static constexpr size_t OFF_U      = 2555904;      // 8192*64
static constexpr size_t OFF_GATE   = 5177344;      // 8192
static constexpr size_t OFF_GCUM   = 5185536;      // 8192
static constexpr size_t OFF_GV     = 5193728;      // 8192*256
static constexpr size_t OFF_CTX    = 7290880;      // 8192*256 (scaled cumsum of x)
static constexpr size_t OFF_H      = 11485184;     // 8192*256
static constexpr size_t OFF_CSUM   = 13582336;     // 4*32*256
static constexpr size_t OFF_DS     = 13615104;     // 4*32*64*256
static constexpr size_t OFF_COMB   = 15712256;     // 8192*256
static constexpr size_t OFF_LN     = 17809408;     // 8192*256
static constexpr size_t OFF_CSUM2  = 19906560;     // 4*32*64
static constexpr size_t TOTAL_F    = 19914752;

__device__ float g_buf[TOTAL_F];

// ---------------- tf32 mma helpers ----------------------------------------
__device__ __forceinline__ uint32_t f2tf(float f) {
    uint32_t u;
    asm("cvt.rna.tf32.f32 %0, %1;" : "=r"(u) : "f"(f));
    return u;
}

__device__ __forceinline__ float f2tf_f(float f) { return __uint_as_float(f2tf(f)); }

__device__ __forceinline__ void mma8(float* c, const uint32_t* a, const uint32_t* b) {
    asm volatile(
        "mma.sync.aligned.m16n8k8.row.col.f32.tf32.tf32.f32 "
        "{%0,%1,%2,%3},{%4,%5,%6,%7},{%8,%9},{%0,%1,%2,%3};"
        : "+f"(c[0]), "+f"(c[1]), "+f"(c[2]), "+f"(c[3])
        : "r"(a[0]), "r"(a[1]), "r"(a[2]), "r"(a[3]), "r"(b[0]), "r"(b[1]));
}

// ---------------- tensor-core GEMM -----------------------------------------
// ACT: 0 none, 1 tanh*pi, 2 gelu, 3 tanh*pi->cos/sin packed (stride 64),
//      4 (v+bias)*addRow[row] (gate fuse),
//      5 pack-ac: C[row*64+col]=addRow(pc)[lrow*32+col]*v; +32 with resid(ps)
// CONCAT: A covers k<Dc, A2 covers k>=Dc (both row stride Dc)
template<int BM, int BN, int MT, int NT, int ACT, int SPLIT, int CONCAT>
__global__ __launch_bounds__(256) void tgemm_k(
    const float* __restrict__ A, const float* __restrict__ A2,
    const float* __restrict__ W,
    const float* __restrict__ bias, const float* __restrict__ addRow,
    const float* __restrict__ resid, float* __restrict__ C,
    int N, int K)
{
    static_assert(BM == 4 * MT * 16 && BN == 2 * NT * 8, "tile mismatch");
    const int BK = 32;
    __shared__ float As[BM][BK + 4];
    __shared__ float Ws[BK][BN + 8];
    int tid = threadIdx.x;
    int warp = tid >> 5, lane = tid & 31;
    int wm = warp >> 1, wn = warp & 1;
    int g = lane >> 2, tig = lane & 3;
    int bm = blockIdx.y * BM, bn = blockIdx.x * BN;

    float acc[MT][NT][4] = {};

    for (int k0 = 0; k0 < K; k0 += BK) {
        constexpr int AF4 = BM * BK / 4 / 256;
#pragma unroll
        for (int i = 0; i < AF4; i++) {
            int id = tid + 256 * i;
            int r = id >> 3, c4 = (id & 7) << 2;
            float4 v;
            if (CONCAT) {
                const float* src = (k0 < Dc) ? (A + (size_t)(bm + r) * Dc + k0 + c4)
                                             : (A2 + (size_t)(bm + r) * Dc + (k0 - Dc) + c4);
                v = *reinterpret_cast<const float4*>(src);
            } else {
                v = *reinterpret_cast<const float4*>(A + (size_t)(bm + r) * K + k0 + c4);
            }
            if (!SPLIT) {
                v.x = f2tf_f(v.x); v.y = f2tf_f(v.y);
                v.z = f2tf_f(v.z); v.w = f2tf_f(v.w);
            }
            *reinterpret_cast<float4*>(&As[r][c4]) = v;
        }
        constexpr int WF4 = BK * BN / 4 / 256;
#pragma unroll
        for (int i = 0; i < WF4; i++) {
            int id = tid + 256 * i;
            int r = id / (BN / 4), c4 = (id % (BN / 4)) << 2;
            float4 v = *reinterpret_cast<const float4*>(W + (size_t)(k0 + r) * N + bn + c4);
            if (!SPLIT) {
                v.x = f2tf_f(v.x); v.y = f2tf_f(v.y);
                v.z = f2tf_f(v.z); v.w = f2tf_f(v.w);
            }
            *reinterpret_cast<float4*>(&Ws[r][c4]) = v;
        }
        __syncthreads();
#pragma unroll
        for (int ks = 0; ks < 4; ks++) {
            int kk = ks * 8;
            uint32_t ah[MT][4], al[MT][4];
#pragma unroll
            for (int mt = 0; mt < MT; mt++) {
                int r0 = wm * MT * 16 + mt * 16 + g;
                float f0 = As[r0][kk + tig],     f1 = As[r0 + 8][kk + tig];
                float f2 = As[r0][kk + tig + 4], f3 = As[r0 + 8][kk + tig + 4];
                if (SPLIT) {
                    ah[mt][0] = f2tf(f0); al[mt][0] = f2tf(f0 - __uint_as_float(ah[mt][0]));
                    ah[mt][1] = f2tf(f1); al[mt][1] = f2tf(f1 - __uint_as_float(ah[mt][1]));
                    ah[mt][2] = f2tf(f2); al[mt][2] = f2tf(f2 - __uint_as_float(ah[mt][2]));
                    ah[mt][3] = f2tf(f3); al[mt][3] = f2tf(f3 - __uint_as_float(ah[mt][3]));
                } else {
                    ah[mt][0] = __float_as_uint(f0); ah[mt][1] = __float_as_uint(f1);
                    ah[mt][2] = __float_as_uint(f2); ah[mt][3] = __float_as_uint(f3);
                }
            }
            uint32_t bh[NT][2], bl[NT][2];
#pragma unroll
            for (int nt = 0; nt < NT; nt++) {
                int cn = wn * NT * 8 + nt * 8 + g;
                float f0 = Ws[kk + tig][cn], f1 = Ws[kk + tig + 4][cn];
                if (SPLIT) {
                    bh[nt][0] = f2tf(f0); bl[nt][0] = f2tf(f0 - __uint_as_float(bh[nt][0]));
                    bh[nt][1] = f2tf(f1); bl[nt][1] = f2tf(f1 - __uint_as_float(bh[nt][1]));
                } else {
                    bh[nt][0] = __float_as_uint(f0); bh[nt][1] = __float_as_uint(f1);
                }
            }
#pragma unroll
            for (int mt = 0; mt < MT; mt++)
#pragma unroll
                for (int nt = 0; nt < NT; nt++) {
                    mma8(acc[mt][nt], ah[mt], bh[nt]);
                    if (SPLIT) {
                        mma8(acc[mt][nt], al[mt], bh[nt]);
                        mma8(acc[mt][nt], ah[mt], bl[nt]);
                    }
                }
        }
        __syncthreads();
    }

#pragma unroll
    for (int mt = 0; mt < MT; mt++)
#pragma unroll
        for (int nt = 0; nt < NT; nt++) {
            int r0 = bm + wm * MT * 16 + mt * 16 + g;
            int col = bn + wn * NT * 8 + nt * 8 + 2 * tig;
#pragma unroll
            for (int h2 = 0; h2 < 2; h2++) {
                int row = r0 + h2 * 8;
                int lrow = row & (Lc - 1);
                float v0 = acc[mt][nt][h2 * 2 + 0];
                float v1 = acc[mt][nt][h2 * 2 + 1];
                if (bias) { v0 += bias[col]; v1 += bias[col + 1]; }
                if (ACT == 4) {
                    float gt = addRow[row];
                    v0 *= gt; v1 *= gt;
                } else if (ACT != 5 && addRow) {
                    v0 += addRow[(size_t)lrow * N + col];
                    v1 += addRow[(size_t)lrow * N + col + 1];
                }
                if (ACT == 1) { v0 = tanhf(v0) * PIF; v1 = tanhf(v1) * PIF; }
                else if (ACT == 2) {
                    v0 = 0.5f * v0 * (1.0f + erff(v0 * 0.70710678118654752f));
                    v1 = 0.5f * v1 * (1.0f + erff(v1 * 0.70710678118654752f));
                }
                if (ACT == 3) {
                    v0 = tanhf(v0) * PIF; v1 = tanhf(v1) * PIF;
                    C[(size_t)row * 64 + col]          = cosf(v0);
                    C[(size_t)row * 64 + 32 + col]     = sinf(v0);
                    C[(size_t)row * 64 + col + 1]      = cosf(v1);
                    C[(size_t)row * 64 + 32 + col + 1] = sinf(v1);
                } else if (ACT == 5) {
                    float pc0 = addRow[(size_t)lrow * 32 + col];
                    float pc1 = addRow[(size_t)lrow * 32 + col + 1];
                    float ps0 = resid[(size_t)lrow * 32 + col];
                    float ps1 = resid[(size_t)lrow * 32 + col + 1];
                    C[(size_t)row * 64 + col]          = pc0 * v0;
                    C[(size_t)row * 64 + 32 + col]     = ps0 * v0;
                    C[(size_t)row * 64 + col + 1]      = pc1 * v1;
                    C[(size_t)row * 64 + 32 + col + 1] = ps1 * v1;
                } else {
                    if (resid) {
                        v0 += resid[(size_t)row * N + col];
                        v1 += resid[(size_t)row * N + col + 1];
                    }
                    *reinterpret_cast<float2*>(&C[(size_t)row * N + col]) =
                        make_float2(v0, v1);
                }
            }
        }
}

// ---------------- pos precompute -------------------------------------------
__global__ void pos_pre_k(const float* __restrict__ ph, const float* __restrict__ w_off,
                          const float* __restrict__ b_off,
                          float* __restrict__ pc, float* __restrict__ ps,
                          float* __restrict__ pcon)
{
    int idx = blockIdx.x * blockDim.x + threadIdx.x;
    if (idx >= Lc * Pc) return;
    int l = idx >> 5, p = idx & 31;
    float s = b_off[p];
#pragma unroll
    for (int q = 0; q < Pc; q++) s += ph[l * Pc + q] * w_off[(Dc + q) * Pc + p];
    pcon[idx] = s;
    float v = ph[idx];
    pc[idx] = cosf(v);
    ps[idx] = sinf(v);
}

// ---------------- small kernels --------------------------------------------
__global__ void gate_k(const float* __restrict__ x, const float* __restrict__ w,
                       const float* __restrict__ b, float* __restrict__ gate)
{
    int warp = (blockIdx.x * blockDim.x + threadIdx.x) >> 5;
    int lane = threadIdx.x & 31;
    if (warp >= Mc) return;
    const float* xr = x + (size_t)warp * Dc;
    float s = 0.f;
#pragma unroll
    for (int i = 0; i < Dc / 32; i++) s += xr[lane + 32 * i] * w[lane + 32 * i];
#pragma unroll
    for (int o = 16; o; o >>= 1) s += __shfl_xor_sync(0xffffffffu, s, o);
    if (lane == 0) gate[warp] = 1.0f / (1.0f + expf(-(s + b[0])));
}

// ---------------- chunked scans --------------------------------------------
__global__ void scan_chunk_sums_k(const float* __restrict__ in, float* __restrict__ csum,
                                  int F, int inStride)
{
    int bc = blockIdx.x, b = bc / NCc, c = bc % NCc, f = threadIdx.x;
    const float* p = in + ((size_t)b * Lc + c * CHc) * inStride + f;
    float s = 0.f;
    for (int i = 0; i < CHc; i++) s += p[(size_t)i * inStride];
    csum[(size_t)bc * F + f] = s;
}

__global__ void scan_prefix_k(float* __restrict__ csum, int F)
{
    int b = blockIdx.x, f = threadIdx.x;
    float carry = 0.f;
    for (int c = 0; c < NCc; c++) {
        size_t idx = ((size_t)b * NCc + c) * F + f;
        float v = csum[idx];
        csum[idx] = carry;
        carry += v;
    }
}

// scan apply with per-row 1/(l+1) scale: ctx = cumsum(x)/pos (dense [M,256])
__global__ void scan_apply_scale_k(const float* __restrict__ in, const float* __restrict__ csum,
                                   float* __restrict__ ctx)
{
    int bc = blockIdx.x, b = bc / NCc, c = bc % NCc, f = threadIdx.x;
    float carry = csum[(size_t)bc * 256 + f];
    const float* p = in + ((size_t)b * Lc + c * CHc) * 256 + f;
    float* q = ctx + ((size_t)b * Lc + c * CHc) * 256 + f;
    for (int i = 0; i < CHc; i++) {
        carry += p[(size_t)i * 256];
        q[(size_t)i * 256] = carry * (1.0f / (float)(c * CHc + i + 1));
    }
}

// fused: cumsum of ac over this chunk (to shared) + posret epilogue
__global__ __launch_bounds__(64) void scan_apply_posret_k(
    const float* __restrict__ ac, const float* __restrict__ csum,
    const float* __restrict__ offp, const float* __restrict__ pc,
    const float* __restrict__ ps, float* __restrict__ pr)
{
    __shared__ float sh[64][65];
    int bc = blockIdx.x, f = threadIdx.x;
    size_t rowbase = (size_t)bc * 64;
    float carry = csum[(size_t)bc * 64 + f];
    const float* p = ac + rowbase * 64 + f;
    for (int i = 0; i < CHc; i++) {
        carry += p[(size_t)i * 64];
        sh[i][f] = carry;
    }
    __syncthreads();
#pragma unroll
    for (int j = 0; j < 32; j++) {
        int idx = j * 64 + f;
        int i = idx >> 5, pp = idx & 31;
        size_t m = rowbase + i;
        int l = (int)(m & (Lc - 1));
        float o = offp[m * 32 + pp];
        float oc = cosf(o), os = sinf(o);
        float pcv = pc[l * 32 + pp], psv = ps[l * 32 + pp];
        float qc = pcv * oc - psv * os;
        float qs = psv * oc + pcv * os;
        pr[m * 32 + pp] = (sh[i][pp] * qc + sh[i][32 + pp] * qs) * INV_SQRT_P;
    }
}

__global__ void gate_scan_k(const float* __restrict__ g, float* __restrict__ gc)
{
    int b = blockIdx.x, t = threadIdx.x;
    const float* p = g + b * Lc + t * CHc;
    float s = 0.f;
    for (int i = 0; i < CHc; i++) s += p[i];
    float xv = s;
#pragma unroll
    for (int o = 1; o < 32; o <<= 1) {
        float v = __shfl_up_sync(0xffffffffu, xv, o);
        if (t >= o) xv += v;
    }
    float carry = xv - s;
    float* q = gc + b * Lc + t * CHc;
    for (int i = 0; i < CHc; i++) { carry += p[i]; q[i] = carry; }
}

// ---------------- chunk state delta via tf32 mma ---------------------------
__global__ __launch_bounds__(256) void chunk_delta_k(const float* __restrict__ U,
                                                     const float* __restrict__ GV,
                                                     float* __restrict__ dS)
{
    __shared__ float Us[64][72];
    __shared__ float Gs[64][72];
    int bc = blockIdx.x;
    size_t rowbase = (size_t)bc * 64;
    int tid = threadIdx.x;
    int warp = tid >> 5, lane = tid & 31;
    int wm = warp >> 2, wn = warp & 3;
    int g = lane >> 2, tig = lane & 3;

#pragma unroll
    for (int i = 0; i < 4; i++) {
        int id = tid + 256 * i;
        int t = id >> 4, f = (id & 15) << 2;
        float4 v = *reinterpret_cast<const float4*>(U + (rowbase + t) * 64 + f);
        v.x = f2tf_f(v.x); v.y = f2tf_f(v.y); v.z = f2tf_f(v.z); v.w = f2tf_f(v.w);
        *reinterpret_cast<float4*>(&Us[t][f]) = v;
    }

    for (int dt = 0; dt < 4; dt++) {
        __syncthreads();
#pragma unroll
        for (int i = 0; i < 4; i++) {
            int id = tid + 256 * i;
            int t = id >> 4, d = (id & 15) << 2;
            float4 v = *reinterpret_cast<const float4*>(GV + (rowbase + t) * 256 + dt * 64 + d);
            v.x = f2tf_f(v.x); v.y = f2tf_f(v.y); v.z = f2tf_f(v.z); v.w = f2tf_f(v.w);
            *reinterpret_cast<float4*>(&Gs[t][d]) = v;
        }
        __syncthreads();

        float acc[2][2][4] = {};
#pragma unroll
        for (int ks = 0; ks < 8; ks++) {
            int kk = ks * 8;
            uint32_t a[2][4], b[2][2];
#pragma unroll
            for (int mt = 0; mt < 2; mt++) {
                int f0 = wm * 32 + mt * 16 + g;
                a[mt][0] = __float_as_uint(Us[kk + tig][f0]);
                a[mt][1] = __float_as_uint(Us[kk + tig][f0 + 8]);
                a[mt][2] = __float_as_uint(Us[kk + tig + 4][f0]);
                a[mt][3] = __float_as_uint(Us[kk + tig + 4][f0 + 8]);
            }
#pragma unroll
            for (int nt = 0; nt < 2; nt++) {
                int d0 = wn * 16 + nt * 8 + g;
                b[nt][0] = __float_as_uint(Gs[kk + tig][d0]);
                b[nt][1] = __float_as_uint(Gs[kk + tig + 4][d0]);
            }
#pragma unroll
            for (int mt = 0; mt < 2; mt++)
#pragma unroll
                for (int nt = 0; nt < 2; nt++) mma8(acc[mt][nt], a[mt], b[nt]);
        }
#pragma unroll
        for (int mt = 0; mt < 2; mt++)
#pragma unroll
            for (int nt = 0; nt < 2; nt++) {
                int f0 = wm * 32 + mt * 16 + g;
                int d = dt * 64 + wn * 16 + nt * 8 + 2 * tig;
#pragma unroll
                for (int h2 = 0; h2 < 2; h2++) {
                    *reinterpret_cast<float2*>(&dS[((size_t)bc * 64 + f0 + h2 * 8) * 256 + d]) =
                        make_float2(acc[mt][nt][h2 * 2], acc[mt][nt][h2 * 2 + 1]);
                }
            }
    }
}

// ---------------- exclusive prefix of chunk states -------------------------
__global__ void state_prefix_k(float* __restrict__ dS)
{
    int idx = blockIdx.x * blockDim.x + threadIdx.x;
    int b = idx / (64 * 256);
    int fd = idx % (64 * 256);
    float carry = 0.f;
    for (int c = 0; c < NCc; c++) {
        size_t o = ((size_t)(b * NCc + c)) * 64 * 256 + fd;
        float v = dS[o];
        dS[o] = carry;
        carry += v;
    }
}

// ---------------- kv pass3 via tf32 mma + fused layernorm -------------------
// per block (64 rows): S = mask(Kq @ U^T); out = (S@GV + Kq@Spre)*scl + comb; LN
static constexpr int P3_PITCH = 68;
static constexpr size_t SMEM_P3 = 5 * 64 * P3_PITCH * sizeof(float);

__global__ __launch_bounds__(256) void kv_pass3_mma_k(
    const float* __restrict__ Kq, const float* __restrict__ U,
    const float* __restrict__ GV, const float* __restrict__ Spre,
    const float* __restrict__ gcum, const float* __restrict__ comb,
    const float* __restrict__ lng, const float* __restrict__ lnbv,
    float* __restrict__ outb)
{
    extern __shared__ float dyn[];
    float (*Kqs)[P3_PITCH] = reinterpret_cast<float(*)[P3_PITCH]>(dyn);
    float (*Us)[P3_PITCH]  = reinterpret_cast<float(*)[P3_PITCH]>(dyn + 64 * P3_PITCH);
    float (*Ss)[P3_PITCH]  = reinterpret_cast<float(*)[P3_PITCH]>(dyn + 2 * 64 * P3_PITCH);
    float (*P1)[P3_PITCH]  = reinterpret_cast<float(*)[P3_PITCH]>(dyn + 3 * 64 * P3_PITCH);
    float (*P2)[P3_PITCH]  = reinterpret_cast<float(*)[P3_PITCH]>(dyn + 4 * 64 * P3_PITCH);
    __shared__ float ws[4][64], ws2[4][64];

    int bc = blockIdx.x;
    size_t rowbase = (size_t)bc * 64;
    int tid = threadIdx.x;
    int warp = tid >> 5, lane = tid & 31;
    int wm = warp >> 2, wn = warp & 3;          // 2 (M) x 4 (N)
    int g = lane >> 2, tig = lane & 3;

    // load Kq, U tiles (tf32)
#pragma unroll
    for (int i = 0; i < 4; i++) {
        int id = tid + 256 * i;
        int t = id >> 4, f = (id & 15) << 2;
        float4 v = *reinterpret_cast<const float4*>(Kq + (rowbase + t) * 64 + f);
        v.x = f2tf_f(v.x); v.y = f2tf_f(v.y); v.z = f2tf_f(v.z); v.w = f2tf_f(v.w);
        *reinterpret_cast<float4*>(&Kqs[t][f]) = v;
        float4 w = *reinterpret_cast<const float4*>(U + (rowbase + t) * 64 + f);
        w.x = f2tf_f(w.x); w.y = f2tf_f(w.y); w.z = f2tf_f(w.z); w.w = f2tf_f(w.w);
        *reinterpret_cast<float4*>(&Us[t][f]) = w;
    }
    __syncthreads();

    // ---- score phase: S[l][t] = sum_f Kq[l][f] * U[t][f], masked t<=l ----
    {
        float sacc[2][2][4] = {};
#pragma unroll
        for (int ks = 0; ks < 8; ks++) {
            int kk = ks * 8;
            uint32_t a[2][4], b[2][2];
#pragma unroll
            for (int mt = 0; mt < 2; mt++) {
                int r0 = wm * 32 + mt * 16 + g;
                a[mt][0] = __float_as_uint(Kqs[r0][kk + tig]);
                a[mt][1] = __float_as_uint(Kqs[r0 + 8][kk + tig]);
                a[mt][2] = __float_as_uint(Kqs[r0][kk + tig + 4]);
                a[mt][3] = __float_as_uint(Kqs[r0 + 8][kk + tig + 4]);
            }
#pragma unroll
            for (int nt = 0; nt < 2; nt++) {
                int cn = wn * 16 + nt * 8 + g;
                b[nt][0] = __float_as_uint(Us[cn][kk + tig]);
                b[nt][1] = __float_as_uint(Us[cn][kk + tig + 4]);
            }
#pragma unroll
            for (int mt = 0; mt < 2; mt++)
#pragma unroll
                for (int nt = 0; nt < 2; nt++) mma8(sacc[mt][nt], a[mt], b[nt]);
        }
        // mask + store (tf32)
#pragma unroll
        for (int mt = 0; mt < 2; mt++)
#pragma unroll
            for (int nt = 0; nt < 2; nt++)
#pragma unroll
                for (int h2 = 0; h2 < 2; h2++) {
                    int row = wm * 32 + mt * 16 + h2 * 8 + g;
                    int col = wn * 16 + nt * 8 + 2 * tig;
                    float v0 = (col     <= row) ? sacc[mt][nt][h2 * 2]     : 0.f;
                    float v1 = (col + 1 <= row) ? sacc[mt][nt][h2 * 2 + 1] : 0.f;
                    Ss[row][col]     = f2tf_f(v0);
                    Ss[row][col + 1] = f2tf_f(v1);
                }
    }
    __syncthreads();

    // ---- main phase: out = S@GV + Kq@Spre over 4 panels of 64 cols ----
    float val[4][2][2][4];
#pragma unroll
    for (int p = 0; p < 4; p++)
#pragma unroll
        for (int mt = 0; mt < 2; mt++)
#pragma unroll
            for (int nt = 0; nt < 2; nt++)
#pragma unroll
                for (int j = 0; j < 4; j++) val[p][mt][nt][j] = 0.f;

    for (int p = 0; p < 4; p++) {
#pragma unroll
        for (int i = 0; i < 4; i++) {
            int id = tid + 256 * i;
            int t = id >> 4, d = (id & 15) << 2;
            float4 v = *reinterpret_cast<const float4*>(GV + (rowbase + t) * 256 + p * 64 + d);
            v.x = f2tf_f(v.x); v.y = f2tf_f(v.y); v.z = f2tf_f(v.z); v.w = f2tf_f(v.w);
            *reinterpret_cast<float4*>(&P1[t][d]) = v;
            float4 w = *reinterpret_cast<const float4*>(Spre + ((size_t)bc * 64 + t) * 256 + p * 64 + d);
            w.x = f2tf_f(w.x); w.y = f2tf_f(w.y); w.z = f2tf_f(w.z); w.w = f2tf_f(w.w);
            *reinterpret_cast<float4*>(&P2[t][d]) = w;
        }
        __syncthreads();
#pragma unroll
        for (int ks = 0; ks < 8; ks++) {
            int kk = ks * 8;
            uint32_t a1[2][4], a2[2][4], b1[2][2], b2[2][2];
#pragma unroll
            for (int mt = 0; mt < 2; mt++) {
                int r0 = wm * 32 + mt * 16 + g;
                a1[mt][0] = __float_as_uint(Ss[r0][kk + tig]);
                a1[mt][1] = __float_as_uint(Ss[r0 + 8][kk + tig]);
                a1[mt][2] = __float_as_uint(Ss[r0][kk + tig + 4]);
                a1[mt][3] = __float_as_uint(Ss[r0 + 8][kk + tig + 4]);
                a2[mt][0] = __float_as_uint(Kqs[r0][kk + tig]);
                a2[mt][1] = __float_as_uint(Kqs[r0 + 8][kk + tig]);
                a2[mt][2] = __float_as_uint(Kqs[r0][kk + tig + 4]);
                a2[mt][3] = __float_as_uint(Kqs[r0 + 8][kk + tig + 4]);
            }
#pragma unroll
            for (int nt = 0; nt < 2; nt++) {
                int cn = wn * 16 + nt * 8 + g;
                b1[nt][0] = __float_as_uint(P1[kk + tig][cn]);
                b1[nt][1] = __float_as_uint(P1[kk + tig + 4][cn]);
                b2[nt][0] = __float_as_uint(P2[kk + tig][cn]);
                b2[nt][1] = __float_as_uint(P2[kk + tig + 4][cn]);
            }
#pragma unroll
            for (int mt = 0; mt < 2; mt++)
#pragma unroll
                for (int nt = 0; nt < 2; nt++) {
                    mma8(val[p][mt][nt], a1[mt], b1[nt]);
                    mma8(val[p][mt][nt], a2[mt], b2[nt]);
                }
        }
        __syncthreads();
    }

    // ---- epilogue: scale + comb, LN partials ----
    float scl4[4];
#pragma unroll
    for (int mt = 0; mt < 2; mt++)
#pragma unroll
        for (int h2 = 0; h2 < 2; h2++) {
            int row = wm * 32 + mt * 16 + h2 * 8 + g;
            float gc = gcum[rowbase + row];
            scl4[mt * 2 + h2] = rsqrtf(fmaxf(gc, 1.0f)) * INV_SQRT_P;
        }
    float s[4] = {}, s2[4] = {};
#pragma unroll
    for (int p = 0; p < 4; p++)
#pragma unroll
        for (int mt = 0; mt < 2; mt++)
#pragma unroll
            for (int nt = 0; nt < 2; nt++)
#pragma unroll
                for (int h2 = 0; h2 < 2; h2++) {
                    int row = wm * 32 + mt * 16 + h2 * 8 + g;
                    int col = p * 64 + wn * 16 + nt * 8 + 2 * tig;
                    int slot = mt * 2 + h2;
                    float2 cb = *reinterpret_cast<const float2*>(
                        &comb[(rowbase + row) * 256 + col]);
                    float v0 = cb.x + val[p][mt][nt][h2 * 2]     * scl4[slot];
                    float v1 = cb.y + val[p][mt][nt][h2 * 2 + 1] * scl4[slot];
                    val[p][mt][nt][h2 * 2] = v0;
                    val[p][mt][nt][h2 * 2 + 1] = v1;
                    s[slot] += v0 + v1;
                    s2[slot] += v0 * v0 + v1 * v1;
                }
#pragma unroll
    for (int o = 1; o <= 2; o <<= 1)
#pragma unroll
        for (int i = 0; i < 4; i++) {
            s[i]  += __shfl_xor_sync(0xffffffffu, s[i],  o);
            s2[i] += __shfl_xor_sync(0xffffffffu, s2[i], o);
        }
    if (tig == 0) {
#pragma unroll
        for (int mt = 0; mt < 2; mt++)
#pragma unroll
            for (int h2 = 0; h2 < 2; h2++) {
                int row = wm * 32 + mt * 16 + h2 * 8 + g;
                ws[wn][row]  = s[mt * 2 + h2];
                ws2[wn][row] = s2[mt * 2 + h2];
            }
    }
    __syncthreads();
    float mean4[4], rstd4[4];
#pragma unroll
    for (int mt = 0; mt < 2; mt++)
#pragma unroll
        for (int h2 = 0; h2 < 2; h2++) {
            int row = wm * 32 + mt * 16 + h2 * 8 + g;
            float St = ws[0][row] + ws[1][row] + ws[2][row] + ws[3][row];
            float S2t = ws2[0][row] + ws2[1][row] + ws2[2][row] + ws2[3][row];
            float mean = St * (1.0f / 256.0f);
            float var = S2t * (1.0f / 256.0f) - mean * mean;
            mean4[mt * 2 + h2] = mean;
            rstd4[mt * 2 + h2] = rsqrtf(var + 1e-5f);
        }
#pragma unroll
    for (int p = 0; p < 4; p++)
#pragma unroll
        for (int nt = 0; nt < 2; nt++) {
            int col = p * 64 + wn * 16 + nt * 8 + 2 * tig;
            float g0 = lng[col], g1 = lng[col + 1];
            float b0 = lnbv[col], b1 = lnbv[col + 1];
#pragma unroll
            for (int mt = 0; mt < 2; mt++)
#pragma unroll
                for (int h2 = 0; h2 < 2; h2++) {
                    int row = wm * 32 + mt * 16 + h2 * 8 + g;
                    int slot = mt * 2 + h2;
                    float v0 = (val[p][mt][nt][h2 * 2]     - mean4[slot]) * rstd4[slot] * g0 + b0;
                    float v1 = (val[p][mt][nt][h2 * 2 + 1] - mean4[slot]) * rstd4[slot] * g1 + b1;
                    *reinterpret_cast<float2*>(&outb[(rowbase + row) * 256 + col]) =
                        make_float2(v0, v1);
                }
        }
}

// ---------------- stream/event context (created once, outside capture) -----
namespace {
struct Ctx {
    cudaStream_t s1, s2;
    cudaEvent_t eR1, eR2, eGV, eA, eBC;
    Ctx() {
        cudaStreamCreateWithFlags(&s1, cudaStreamNonBlocking);
        cudaStreamCreateWithFlags(&s2, cudaStreamNonBlocking);
        cudaEventCreateWithFlags(&eR1, cudaEventDisableTiming);
        cudaEventCreateWithFlags(&eR2, cudaEventDisableTiming);
        cudaEventCreateWithFlags(&eGV, cudaEventDisableTiming);
        cudaEventCreateWithFlags(&eA, cudaEventDisableTiming);
        cudaEventCreateWithFlags(&eBC, cudaEventDisableTiming);
        cudaFuncSetAttribute(kv_pass3_mma_k,
                             cudaFuncAttributeMaxDynamicSharedMemorySize, (int)SMEM_P3);
    }
};
Ctx& C() { static Ctx c; return c; }
}

// ---------------- host launch -----------------------------------------------
extern "C" void kernel_launch(void* const* d_in, const int* in_sizes, int n_in,
                              void* d_out, int out_size)
{
    (void)in_sizes; (void)n_in; (void)out_size;
    const float* x        = (const float*)d_in[0];
    const float* pos_ph   = (const float*)d_in[1];
    const float* w_mem1v  = (const float*)d_in[2];
    const float* b_mem1v  = (const float*)d_in[3];
    const float* w_mem1o  = (const float*)d_in[4];
    const float* b_mem1o  = (const float*)d_in[5];
    const float* w_off    = (const float*)d_in[6];
    const float* b_off    = (const float*)d_in[7];
    const float* w_key    = (const float*)d_in[8];
    const float* b_key    = (const float*)d_in[9];
    const float* w_val    = (const float*)d_in[10];
    const float* b_val    = (const float*)d_in[11];
    const float* w_sk1    = (const float*)d_in[12];
    const float* b_sk1    = (const float*)d_in[13];
    const float* w_sk2    = (const float*)d_in[14];
    const float* b_sk2    = (const float*)d_in[15];
    const float* w_gate   = (const float*)d_in[16];
    const float* b_gate   = (const float*)d_in[17];
    const float* ln_g     = (const float*)d_in[18];
    const float* ln_b     = (const float*)d_in[19];
    const float* w_out    = (const float*)d_in[20];
    const float* b_out    = (const float*)d_in[21];
    float* out = (float*)d_out;

    float* buf = nullptr;
    cudaGetSymbolAddress((void**)&buf, g_buf);
    float* offp  = buf + OFF_OFFP;
    float* pcon  = buf + OFF_PCON;
    float* pc    = buf + OFF_PC;
    float* ps    = buf + OFF_PS;
    float* ac    = buf + OFF_AC;
    float* pr    = buf + OFF_POSRET;
    float* kq    = buf + OFF_KQ;
    float* u     = buf + OFF_U;
    float* gate  = buf + OFF_GATE;
    float* gcum  = buf + OFF_GCUM;
    float* gv    = buf + OFF_GV;
    float* ctx   = buf + OFF_CTX;
    float* h     = buf + OFF_H;
    float* csum  = buf + OFF_CSUM;
    float* csum2 = buf + OFF_CSUM2;
    float* dS    = buf + OFF_DS;
    float* comb  = buf + OFF_COMB;
    float* lnb   = buf + OFF_LN;

    Ctx& c = C();
    dim3 gS(1, Mc / 64);
    dim3 gW(4, Mc / 128);

    // fork
    cudaEventRecord(c.eR1, 0);
    cudaStreamWaitEvent(c.s1, c.eR1, 0);
    cudaEventRecord(c.eR2, 0);
    cudaStreamWaitEvent(c.s2, c.eR2, 0);

    // ---- path A (s1): mem1 ----
    pos_pre_k<<<(Lc * Pc) / 256, 256, 0, c.s1>>>(pos_ph, w_off, b_off, pc, ps, pcon);
    tgemm_k<64, 32, 1, 2, 5, 0, 0><<<gS, 256, 0, c.s1>>>(x, nullptr, w_mem1v, b_mem1v, pc, ps, ac, Pc, Dc);
    tgemm_k<64, 32, 1, 2, 1, 1, 0><<<gS, 256, 0, c.s1>>>(x, nullptr, w_off, nullptr, pcon, nullptr, offp, Pc, Dc);
    scan_chunk_sums_k<<<Bc * NCc, 64, 0, c.s1>>>(ac, csum2, 64, 64);
    scan_prefix_k<<<Bc, 64, 0, c.s1>>>(csum2, 64);
    scan_apply_posret_k<<<Bc * NCc, 64, 0, c.s1>>>(ac, csum2, offp, pc, ps, pr);
    tgemm_k<128, 64, 2, 4, 0, 0, 0><<<gW, 256, 0, c.s1>>>(pr, nullptr, w_mem1o, b_mem1o, nullptr, nullptr, comb, Dc, Pc);
    cudaEventRecord(c.eA, c.s1);

    // ---- path B/C (s2): gate, values, keys ----
    gate_k<<<Mc / 8, 256, 0, c.s2>>>(x, w_gate, b_gate, gate);
    tgemm_k<128, 64, 2, 4, 4, 0, 0><<<gW, 256, 0, c.s2>>>(x, nullptr, w_val, b_val, gate, nullptr, gv, Dc, Dc);
    cudaEventRecord(c.eGV, c.s2);
    gate_scan_k<<<Bc, 32, 0, c.s2>>>(gate, gcum);
    tgemm_k<64, 32, 1, 2, 3, 1, 0><<<gS, 256, 0, c.s2>>>(x, nullptr, w_key, b_key, nullptr, nullptr, kq, Pc, Dc);
    cudaEventRecord(c.eBC, c.s2);

    // ---- path D (default): storage phases + attention ----
    scan_chunk_sums_k<<<Bc * NCc, 256>>>(x, csum, 256, 256);
    scan_prefix_k<<<Bc, 256>>>(csum, 256);
    scan_apply_scale_k<<<Bc * NCc, 256>>>(x, csum, ctx);
    tgemm_k<128, 64, 2, 4, 2, 0, 1><<<gW, 256>>>(x, ctx, w_sk1, b_sk1, nullptr, nullptr, h, Dc, 2 * Dc);
    tgemm_k<64, 32, 1, 2, 3, 1, 0><<<gS, 256>>>(h, nullptr, w_sk2, b_sk2, nullptr, nullptr, u, Pc, Dc);
    cudaStreamWaitEvent(0, c.eGV, 0);
    chunk_delta_k<<<Bc * NCc, 256>>>(u, gv, dS);
    state_prefix_k<<<(Bc * 64 * 256) / 256, 256>>>(dS);
    cudaStreamWaitEvent(0, c.eA, 0);
    cudaStreamWaitEvent(0, c.eBC, 0);
    kv_pass3_mma_k<<<Bc * NCc, 256, SMEM_P3>>>(kq, u, gv, dS, gcum, comb, ln_g, ln_b, lnb);
    tgemm_k<128, 64, 2, 4, 0, 0, 0><<<gW, 256>>>(lnb, nullptr, w_out, b_out, nullptr, x, out, Dc, Dc);
}

// round 9
// speedup vs baseline: 2.6620x; 1.0351x over previous
#include <cuda_runtime.h>
#include <cstdint>
#include <math.h>

#define Bc 4
#define Lc 2048
#define Dc 256
#define Pc 32
#define Mc 8192
#define NCc 32
#define CHc 64
#define NC2 64
#define CH2 32
#define PIF 3.14159265358979323846f
#define INV_SQRT_P 0.17677669529663688f

// ---------------- scratch (single static device buffer, no allocs) --------
static constexpr size_t OFF_CSUM   = 0;            // 4*64*256 = 65536
static constexpr size_t OFF_OFFP   = 262144;       // 8192*32
static constexpr size_t OFF_PCON   = 524288;       // 2048*32
static constexpr size_t OFF_PC     = 589824;       // 2048*32
static constexpr size_t OFF_PS     = 655360;       // 2048*32
static constexpr size_t OFF_AC     = 720896;       // 8192*64
static constexpr size_t OFF_POSRET = 1245184;      // 8192*32
static constexpr size_t OFF_KQ     = 1769472;      // 8192*64
static constexpr size_t OFF_U      = 2555904;      // 8192*64
static constexpr size_t OFF_GATE   = 5177344;      // 8192
static constexpr size_t OFF_GCUM   = 5185536;      // 8192
static constexpr size_t OFF_GV     = 5193728;      // 8192*256
static constexpr size_t OFF_CTX    = 7290880;      // 8192*256
static constexpr size_t OFF_H      = 11485184;     // 8192*256
static constexpr size_t OFF_DS     = 13615104;     // 4*32*64*256
static constexpr size_t OFF_COMB   = 15712256;     // 8192*256
static constexpr size_t OFF_LN     = 17809408;     // 8192*256
static constexpr size_t OFF_CSUM2  = 19906560;     // 4*32*64
static constexpr size_t TOTAL_F    = 19914752;

__device__ float g_buf[TOTAL_F];

// ---------------- helpers ---------------------------------------------------
__device__ __forceinline__ uint32_t f2tf(float f) {
    uint32_t u;
    asm("cvt.rna.tf32.f32 %0, %1;" : "=r"(u) : "f"(f));
    return u;
}
__device__ __forceinline__ float f2tf_f(float f) { return __uint_as_float(f2tf(f)); }

__device__ __forceinline__ void mma8(float* c, const uint32_t* a, const uint32_t* b) {
    asm volatile(
        "mma.sync.aligned.m16n8k8.row.col.f32.tf32.tf32.f32 "
        "{%0,%1,%2,%3},{%4,%5,%6,%7},{%8,%9},{%0,%1,%2,%3};"
        : "+f"(c[0]), "+f"(c[1]), "+f"(c[2]), "+f"(c[3])
        : "r"(a[0]), "r"(a[1]), "r"(a[2]), "r"(a[3]), "r"(b[0]), "r"(b[1]));
}

__device__ __forceinline__ void cpa16(uint32_t s, const void* g) {
    asm volatile("cp.async.ca.shared.global [%0], [%1], 16;" :: "r"(s), "l"(g));
}

// ---------------- tensor-core GEMM: cp.async 2-stage pipeline ---------------
// ACT: 0 none, 1 tanh*pi, 2 gelu, 3 tanh*pi->cos/sin packed, 4 gate fuse,
//      5 pack-ac. SPLIT: 3-mma tf32 correction. CONCAT: A|A2 virtual concat.
template<int BM, int BN, int MT, int NT, int ACT, int SPLIT, int CONCAT>
__global__ __launch_bounds__(256) void tgemm_k(
    const float* __restrict__ A, const float* __restrict__ A2,
    const float* __restrict__ W,
    const float* __restrict__ bias, const float* __restrict__ addRow,
    const float* __restrict__ resid, float* __restrict__ C,
    int N, int K)
{
    static_assert(BM == 4 * MT * 16 && BN == 2 * NT * 8, "tile mismatch");
    const int BK = 32, AP = BK + 4, WP = BN + 8;
    extern __shared__ float sm[];
    float* Ab = sm;                     // 2 * BM * AP
    float* Wb = sm + 2 * BM * AP;       // 2 * BK * WP
    int tid = threadIdx.x;
    int warp = tid >> 5, lane = tid & 31;
    int wm = warp >> 1, wn = warp & 1;
    int g = lane >> 2, tig = lane & 3;
    int bm = blockIdx.y * BM, bn = blockIdx.x * BN;

    float acc[MT][NT][4] = {};

    auto issue = [&](int k0, int s) {
        constexpr int AF4 = BM * BK / 4 / 256;
#pragma unroll
        for (int i = 0; i < AF4; i++) {
            int id = tid + 256 * i;
            int r = id >> 3, c4 = (id & 7) << 2;
            const float* src;
            if (CONCAT)
                src = (k0 < Dc) ? A + (size_t)(bm + r) * Dc + k0 + c4
                                : A2 + (size_t)(bm + r) * Dc + (k0 - Dc) + c4;
            else
                src = A + (size_t)(bm + r) * K + k0 + c4;
            cpa16((uint32_t)__cvta_generic_to_shared(Ab + (s * BM + r) * AP + c4), src);
        }
        constexpr int WF4 = BK * BN / 4 / 256;
#pragma unroll
        for (int i = 0; i < WF4; i++) {
            int id = tid + 256 * i;
            int r = id / (BN / 4), c4 = (id % (BN / 4)) << 2;
            cpa16((uint32_t)__cvta_generic_to_shared(Wb + (s * BK + r) * WP + c4),
                  W + (size_t)(k0 + r) * N + bn + c4);
        }
        asm volatile("cp.async.commit_group;");
    };

    issue(0, 0);
    int nit = K / BK;
    for (int it = 0; it < nit; it++) {
        asm volatile("cp.async.wait_group 0;");
        __syncthreads();
        if (it + 1 < nit) issue((it + 1) * BK, (it + 1) & 1);
        int sb = it & 1;
        const float* Ac = Ab + sb * BM * AP;
        const float* Wc = Wb + sb * BK * WP;
#pragma unroll
        for (int ks = 0; ks < 4; ks++) {
            int kk = ks * 8;
            uint32_t ah[MT][4], al[MT][4];
#pragma unroll
            for (int mt = 0; mt < MT; mt++) {
                int r0 = wm * MT * 16 + mt * 16 + g;
                float f0 = Ac[r0 * AP + kk + tig],       f1 = Ac[(r0 + 8) * AP + kk + tig];
                float f2 = Ac[r0 * AP + kk + tig + 4],   f3 = Ac[(r0 + 8) * AP + kk + tig + 4];
                if (SPLIT) {
                    ah[mt][0] = f2tf(f0); al[mt][0] = f2tf(f0 - __uint_as_float(ah[mt][0]));
                    ah[mt][1] = f2tf(f1); al[mt][1] = f2tf(f1 - __uint_as_float(ah[mt][1]));
                    ah[mt][2] = f2tf(f2); al[mt][2] = f2tf(f2 - __uint_as_float(ah[mt][2]));
                    ah[mt][3] = f2tf(f3); al[mt][3] = f2tf(f3 - __uint_as_float(ah[mt][3]));
                } else {
                    ah[mt][0] = __float_as_uint(f0); ah[mt][1] = __float_as_uint(f1);
                    ah[mt][2] = __float_as_uint(f2); ah[mt][3] = __float_as_uint(f3);
                }
            }
            uint32_t bh[NT][2], bl[NT][2];
#pragma unroll
            for (int nt = 0; nt < NT; nt++) {
                int cn = wn * NT * 8 + nt * 8 + g;
                float f0 = Wc[(kk + tig) * WP + cn], f1 = Wc[(kk + tig + 4) * WP + cn];
                if (SPLIT) {
                    bh[nt][0] = f2tf(f0); bl[nt][0] = f2tf(f0 - __uint_as_float(bh[nt][0]));
                    bh[nt][1] = f2tf(f1); bl[nt][1] = f2tf(f1 - __uint_as_float(bh[nt][1]));
                } else {
                    bh[nt][0] = __float_as_uint(f0); bh[nt][1] = __float_as_uint(f1);
                }
            }
#pragma unroll
            for (int mt = 0; mt < MT; mt++)
#pragma unroll
                for (int nt = 0; nt < NT; nt++) {
                    mma8(acc[mt][nt], ah[mt], bh[nt]);
                    if (SPLIT) {
                        mma8(acc[mt][nt], al[mt], bh[nt]);
                        mma8(acc[mt][nt], ah[mt], bl[nt]);
                    }
                }
        }
        __syncthreads();
    }

#pragma unroll
    for (int mt = 0; mt < MT; mt++)
#pragma unroll
        for (int nt = 0; nt < NT; nt++) {
            int r0 = bm + wm * MT * 16 + mt * 16 + g;
            int col = bn + wn * NT * 8 + nt * 8 + 2 * tig;
#pragma unroll
            for (int h2 = 0; h2 < 2; h2++) {
                int row = r0 + h2 * 8;
                int lrow = row & (Lc - 1);
                float v0 = acc[mt][nt][h2 * 2 + 0];
                float v1 = acc[mt][nt][h2 * 2 + 1];
                if (bias) { v0 += bias[col]; v1 += bias[col + 1]; }
                if (ACT == 4) {
                    float gt = addRow[row];
                    v0 *= gt; v1 *= gt;
                } else if (ACT != 5 && addRow) {
                    v0 += addRow[(size_t)lrow * N + col];
                    v1 += addRow[(size_t)lrow * N + col + 1];
                }
                if (ACT == 1) { v0 = tanhf(v0) * PIF; v1 = tanhf(v1) * PIF; }
                else if (ACT == 2) {
                    v0 = 0.5f * v0 * (1.0f + erff(v0 * 0.70710678118654752f));
                    v1 = 0.5f * v1 * (1.0f + erff(v1 * 0.70710678118654752f));
                }
                if (ACT == 3) {
                    v0 = tanhf(v0) * PIF; v1 = tanhf(v1) * PIF;
                    C[(size_t)row * 64 + col]          = cosf(v0);
                    C[(size_t)row * 64 + 32 + col]     = sinf(v0);
                    C[(size_t)row * 64 + col + 1]      = cosf(v1);
                    C[(size_t)row * 64 + 32 + col + 1] = sinf(v1);
                } else if (ACT == 5) {
                    float pc0 = addRow[(size_t)lrow * 32 + col];
                    float pc1 = addRow[(size_t)lrow * 32 + col + 1];
                    float ps0 = resid[(size_t)lrow * 32 + col];
                    float ps1 = resid[(size_t)lrow * 32 + col + 1];
                    C[(size_t)row * 64 + col]          = pc0 * v0;
                    C[(size_t)row * 64 + 32 + col]     = ps0 * v0;
                    C[(size_t)row * 64 + col + 1]      = pc1 * v1;
                    C[(size_t)row * 64 + 32 + col + 1] = ps1 * v1;
                } else {
                    if (resid) {
                        v0 += resid[(size_t)row * N + col];
                        v1 += resid[(size_t)row * N + col + 1];
                    }
                    *reinterpret_cast<float2*>(&C[(size_t)row * N + col]) =
                        make_float2(v0, v1);
                }
            }
        }
}

static constexpr int smemg(int BM, int BN) { return 2 * (BM * 36 + 32 * (BN + 8)) * 4; }

// ---------------- pos precompute -------------------------------------------
__global__ void pos_pre_k(const float* __restrict__ ph, const float* __restrict__ w_off,
                          const float* __restrict__ b_off,
                          float* __restrict__ pc, float* __restrict__ ps,
                          float* __restrict__ pcon)
{
    int idx = blockIdx.x * blockDim.x + threadIdx.x;
    if (idx >= Lc * Pc) return;
    int l = idx >> 5, p = idx & 31;
    float s = b_off[p];
#pragma unroll
    for (int q = 0; q < Pc; q++) s += ph[l * Pc + q] * w_off[(Dc + q) * Pc + p];
    pcon[idx] = s;
    float v = ph[idx];
    pc[idx] = cosf(v);
    ps[idx] = sinf(v);
}

// ---------------- small kernels --------------------------------------------
__global__ void gate_k(const float* __restrict__ x, const float* __restrict__ w,
                       const float* __restrict__ b, float* __restrict__ gate)
{
    int warp = (blockIdx.x * blockDim.x + threadIdx.x) >> 5;
    int lane = threadIdx.x & 31;
    if (warp >= Mc) return;
    const float* xr = x + (size_t)warp * Dc;
    float s = 0.f;
#pragma unroll
    for (int i = 0; i < Dc / 32; i++) s += xr[lane + 32 * i] * w[lane + 32 * i];
#pragma unroll
    for (int o = 16; o; o >>= 1) s += __shfl_xor_sync(0xffffffffu, s, o);
    if (lane == 0) gate[warp] = 1.0f / (1.0f + expf(-(s + b[0])));
}

// ---------------- x scan (CH2=32, 3 passes) --------------------------------
__global__ void xscan_sums_k(const float* __restrict__ in, float* __restrict__ csum)
{
    int bc = blockIdx.x, b = bc / NC2, c = bc % NC2, f = threadIdx.x;
    const float* p = in + ((size_t)b * Lc + c * CH2) * 256 + f;
    float s = 0.f;
#pragma unroll
    for (int i = 0; i < CH2; i++) s += p[(size_t)i * 256];
    csum[(size_t)bc * 256 + f] = s;
}

__global__ void xscan_prefix_k(float* __restrict__ csum)
{
    int b = blockIdx.x, f = threadIdx.x;
    size_t base = (size_t)b * NC2 * 256 + f;
    float carry = 0.f;
    float v = csum[base];
    for (int c = 0; c < NC2; c++) {
        size_t idx = base + (size_t)c * 256;
        float vn = (c + 1 < NC2) ? csum[idx + 256] : 0.f;
        csum[idx] = carry;
        carry += v;
        v = vn;
    }
}

__global__ void xscan_apply_k(const float* __restrict__ in, const float* __restrict__ csum,
                              float* __restrict__ ctx)
{
    int bc = blockIdx.x, b = bc / NC2, c = bc % NC2, f = threadIdx.x;
    float carry = csum[(size_t)bc * 256 + f];
    const float* p = in + ((size_t)b * Lc + c * CH2) * 256 + f;
    float* q = ctx + ((size_t)b * Lc + c * CH2) * 256 + f;
#pragma unroll 8
    for (int i = 0; i < CH2; i++) {
        carry += p[(size_t)i * 256];
        q[(size_t)i * 256] = carry * (1.0f / (float)(c * CH2 + i + 1));
    }
}

// ---------------- ac scan (CH=64, F=64) ------------------------------------
__global__ void scan_chunk_sums_k(const float* __restrict__ in, float* __restrict__ csum,
                                  int F, int inStride)
{
    int bc = blockIdx.x, b = bc / NCc, c = bc % NCc, f = threadIdx.x;
    const float* p = in + ((size_t)b * Lc + c * CHc) * inStride + f;
    float s = 0.f;
#pragma unroll 8
    for (int i = 0; i < CHc; i++) s += p[(size_t)i * inStride];
    csum[(size_t)bc * F + f] = s;
}

__global__ void scan_prefix_k(float* __restrict__ csum, int F)
{
    int b = blockIdx.x, f = threadIdx.x;
    float carry = 0.f;
    for (int c = 0; c < NCc; c++) {
        size_t idx = ((size_t)b * NCc + c) * F + f;
        float v = csum[idx];
        csum[idx] = carry;
        carry += v;
    }
}

// fused: cumsum of ac over this chunk (to shared) + posret epilogue
__global__ __launch_bounds__(64) void scan_apply_posret_k(
    const float* __restrict__ ac, const float* __restrict__ csum,
    const float* __restrict__ offp, const float* __restrict__ pc,
    const float* __restrict__ ps, float* __restrict__ pr)
{
    __shared__ float sh[64][65];
    int bc = blockIdx.x, f = threadIdx.x;
    size_t rowbase = (size_t)bc * 64;
    float carry = csum[(size_t)bc * 64 + f];
    const float* p = ac + rowbase * 64 + f;
#pragma unroll 8
    for (int i = 0; i < CHc; i++) {
        carry += p[(size_t)i * 64];
        sh[i][f] = carry;
    }
    __syncthreads();
#pragma unroll
    for (int j = 0; j < 32; j++) {
        int idx = j * 64 + f;
        int i = idx >> 5, pp = idx & 31;
        size_t m = rowbase + i;
        int l = (int)(m & (Lc - 1));
        float o = offp[m * 32 + pp];
        float oc = cosf(o), os = sinf(o);
        float pcv = pc[l * 32 + pp], psv = ps[l * 32 + pp];
        float qc = pcv * oc - psv * os;
        float qs = psv * oc + pcv * os;
        pr[m * 32 + pp] = (sh[i][pp] * qc + sh[i][32 + pp] * qs) * INV_SQRT_P;
    }
}

__global__ void gate_scan_k(const float* __restrict__ g, float* __restrict__ gc)
{
    int b = blockIdx.x, t = threadIdx.x;
    const float* p = g + b * Lc + t * CHc;
    float s = 0.f;
    for (int i = 0; i < CHc; i++) s += p[i];
    float xv = s;
#pragma unroll
    for (int o = 1; o < 32; o <<= 1) {
        float v = __shfl_up_sync(0xffffffffu, xv, o);
        if (t >= o) xv += v;
    }
    float carry = xv - s;
    float* q = gc + b * Lc + t * CHc;
    for (int i = 0; i < CHc; i++) { carry += p[i]; q[i] = carry; }
}

// ---------------- chunk state delta via tf32 mma ---------------------------
__global__ __launch_bounds__(256) void chunk_delta_k(const float* __restrict__ U,
                                                     const float* __restrict__ GV,
                                                     float* __restrict__ dS)
{
    __shared__ float Us[64][72];
    __shared__ float Gs[64][72];
    int bc = blockIdx.x;
    size_t rowbase = (size_t)bc * 64;
    int tid = threadIdx.x;
    int warp = tid >> 5, lane = tid & 31;
    int wm = warp >> 2, wn = warp & 3;
    int g = lane >> 2, tig = lane & 3;

#pragma unroll
    for (int i = 0; i < 4; i++) {
        int id = tid + 256 * i;
        int t = id >> 4, f = (id & 15) << 2;
        float4 v = *reinterpret_cast<const float4*>(U + (rowbase + t) * 64 + f);
        v.x = f2tf_f(v.x); v.y = f2tf_f(v.y); v.z = f2tf_f(v.z); v.w = f2tf_f(v.w);
        *reinterpret_cast<float4*>(&Us[t][f]) = v;
    }

    for (int dt = 0; dt < 4; dt++) {
        __syncthreads();
#pragma unroll
        for (int i = 0; i < 4; i++) {
            int id = tid + 256 * i;
            int t = id >> 4, d = (id & 15) << 2;
            float4 v = *reinterpret_cast<const float4*>(GV + (rowbase + t) * 256 + dt * 64 + d);
            v.x = f2tf_f(v.x); v.y = f2tf_f(v.y); v.z = f2tf_f(v.z); v.w = f2tf_f(v.w);
            *reinterpret_cast<float4*>(&Gs[t][d]) = v;
        }
        __syncthreads();

        float acc[2][2][4] = {};
#pragma unroll
        for (int ks = 0; ks < 8; ks++) {
            int kk = ks * 8;
            uint32_t a[2][4], b[2][2];
#pragma unroll
            for (int mt = 0; mt < 2; mt++) {
                int f0 = wm * 32 + mt * 16 + g;
                a[mt][0] = __float_as_uint(Us[kk + tig][f0]);
                a[mt][1] = __float_as_uint(Us[kk + tig][f0 + 8]);
                a[mt][2] = __float_as_uint(Us[kk + tig + 4][f0]);
                a[mt][3] = __float_as_uint(Us[kk + tig + 4][f0 + 8]);
            }
#pragma unroll
            for (int nt = 0; nt < 2; nt++) {
                int d0 = wn * 16 + nt * 8 + g;
                b[nt][0] = __float_as_uint(Gs[kk + tig][d0]);
                b[nt][1] = __float_as_uint(Gs[kk + tig + 4][d0]);
            }
#pragma unroll
            for (int mt = 0; mt < 2; mt++)
#pragma unroll
                for (int nt = 0; nt < 2; nt++) mma8(acc[mt][nt], a[mt], b[nt]);
        }
#pragma unroll
        for (int mt = 0; mt < 2; mt++)
#pragma unroll
            for (int nt = 0; nt < 2; nt++) {
                int f0 = wm * 32 + mt * 16 + g;
                int d = dt * 64 + wn * 16 + nt * 8 + 2 * tig;
#pragma unroll
                for (int h2 = 0; h2 < 2; h2++) {
                    *reinterpret_cast<float2*>(&dS[((size_t)bc * 64 + f0 + h2 * 8) * 256 + d]) =
                        make_float2(acc[mt][nt][h2 * 2], acc[mt][nt][h2 * 2 + 1]);
                }
            }
    }
}

// ---------------- exclusive prefix of chunk states (pipelined) --------------
__global__ void state_prefix_k(float* __restrict__ dS)
{
    int idx = blockIdx.x * blockDim.x + threadIdx.x;
    int b = idx >> 14;
    int fd = idx & 16383;
    size_t base = (size_t)b * NCc * 16384 + fd;
    float carry = 0.f;
    float v = dS[base];
    for (int c = 0; c < NCc; c++) {
        size_t o = base + (size_t)c * 16384;
        float vn = (c + 1 < NCc) ? dS[o + 16384] : 0.f;
        dS[o] = carry;
        carry += v;
        v = vn;
    }
}

// ---------------- kv pass3 via tf32 mma + fused layernorm -------------------
static constexpr int P3_PITCH = 68;
static constexpr size_t SMEM_P3 = 5 * 64 * P3_PITCH * sizeof(float);

__global__ __launch_bounds__(256) void kv_pass3_mma_k(
    const float* __restrict__ Kq, const float* __restrict__ U,
    const float* __restrict__ GV, const float* __restrict__ Spre,
    const float* __restrict__ gcum, const float* __restrict__ comb,
    const float* __restrict__ lng, const float* __restrict__ lnbv,
    float* __restrict__ outb)
{
    extern __shared__ float dyn[];
    float (*Kqs)[P3_PITCH] = reinterpret_cast<float(*)[P3_PITCH]>(dyn);
    float (*Us)[P3_PITCH]  = reinterpret_cast<float(*)[P3_PITCH]>(dyn + 64 * P3_PITCH);
    float (*Ss)[P3_PITCH]  = reinterpret_cast<float(*)[P3_PITCH]>(dyn + 2 * 64 * P3_PITCH);
    float (*P1)[P3_PITCH]  = reinterpret_cast<float(*)[P3_PITCH]>(dyn + 3 * 64 * P3_PITCH);
    float (*P2)[P3_PITCH]  = reinterpret_cast<float(*)[P3_PITCH]>(dyn + 4 * 64 * P3_PITCH);
    __shared__ float ws[4][64], ws2[4][64];

    int bc = blockIdx.x;
    size_t rowbase = (size_t)bc * 64;
    int tid = threadIdx.x;
    int warp = tid >> 5, lane = tid & 31;
    int wm = warp >> 2, wn = warp & 3;
    int g = lane >> 2, tig = lane & 3;

#pragma unroll
    for (int i = 0; i < 4; i++) {
        int id = tid + 256 * i;
        int t = id >> 4, f = (id & 15) << 2;
        float4 v = *reinterpret_cast<const float4*>(Kq + (rowbase + t) * 64 + f);
        v.x = f2tf_f(v.x); v.y = f2tf_f(v.y); v.z = f2tf_f(v.z); v.w = f2tf_f(v.w);
        *reinterpret_cast<float4*>(&Kqs[t][f]) = v;
        float4 w = *reinterpret_cast<const float4*>(U + (rowbase + t) * 64 + f);
        w.x = f2tf_f(w.x); w.y = f2tf_f(w.y); w.z = f2tf_f(w.z); w.w = f2tf_f(w.w);
        *reinterpret_cast<float4*>(&Us[t][f]) = w;
    }
    __syncthreads();

    {
        float sacc[2][2][4] = {};
#pragma unroll
        for (int ks = 0; ks < 8; ks++) {
            int kk = ks * 8;
            uint32_t a[2][4], b[2][2];
#pragma unroll
            for (int mt = 0; mt < 2; mt++) {
                int r0 = wm * 32 + mt * 16 + g;
                a[mt][0] = __float_as_uint(Kqs[r0][kk + tig]);
                a[mt][1] = __float_as_uint(Kqs[r0 + 8][kk + tig]);
                a[mt][2] = __float_as_uint(Kqs[r0][kk + tig + 4]);
                a[mt][3] = __float_as_uint(Kqs[r0 + 8][kk + tig + 4]);
            }
#pragma unroll
            for (int nt = 0; nt < 2; nt++) {
                int cn = wn * 16 + nt * 8 + g;
                b[nt][0] = __float_as_uint(Us[cn][kk + tig]);
                b[nt][1] = __float_as_uint(Us[cn][kk + tig + 4]);
            }
#pragma unroll
            for (int mt = 0; mt < 2; mt++)
#pragma unroll
                for (int nt = 0; nt < 2; nt++) mma8(sacc[mt][nt], a[mt], b[nt]);
        }
#pragma unroll
        for (int mt = 0; mt < 2; mt++)
#pragma unroll
            for (int nt = 0; nt < 2; nt++)
#pragma unroll
                for (int h2 = 0; h2 < 2; h2++) {
                    int row = wm * 32 + mt * 16 + h2 * 8 + g;
                    int col = wn * 16 + nt * 8 + 2 * tig;
                    float v0 = (col     <= row) ? sacc[mt][nt][h2 * 2]     : 0.f;
                    float v1 = (col + 1 <= row) ? sacc[mt][nt][h2 * 2 + 1] : 0.f;
                    Ss[row][col]     = f2tf_f(v0);
                    Ss[row][col + 1] = f2tf_f(v1);
                }
    }
    __syncthreads();

    float val[4][2][2][4];
#pragma unroll
    for (int p = 0; p < 4; p++)
#pragma unroll
        for (int mt = 0; mt < 2; mt++)
#pragma unroll
            for (int nt = 0; nt < 2; nt++)
#pragma unroll
                for (int j = 0; j < 4; j++) val[p][mt][nt][j] = 0.f;

    for (int p = 0; p < 4; p++) {
#pragma unroll
        for (int i = 0; i < 4; i++) {
            int id = tid + 256 * i;
            int t = id >> 4, d = (id & 15) << 2;
            float4 v = *reinterpret_cast<const float4*>(GV + (rowbase + t) * 256 + p * 64 + d);
            v.x = f2tf_f(v.x); v.y = f2tf_f(v.y); v.z = f2tf_f(v.z); v.w = f2tf_f(v.w);
            *reinterpret_cast<float4*>(&P1[t][d]) = v;
            float4 w = *reinterpret_cast<const float4*>(Spre + ((size_t)bc * 64 + t) * 256 + p * 64 + d);
            w.x = f2tf_f(w.x); w.y = f2tf_f(w.y); w.z = f2tf_f(w.z); w.w = f2tf_f(w.w);
            *reinterpret_cast<float4*>(&P2[t][d]) = w;
        }
        __syncthreads();
#pragma unroll
        for (int ks = 0; ks < 8; ks++) {
            int kk = ks * 8;
            uint32_t a1[2][4], a2[2][4], b1[2][2], b2[2][2];
#pragma unroll
            for (int mt = 0; mt < 2; mt++) {
                int r0 = wm * 32 + mt * 16 + g;
                a1[mt][0] = __float_as_uint(Ss[r0][kk + tig]);
                a1[mt][1] = __float_as_uint(Ss[r0 + 8][kk + tig]);
                a1[mt][2] = __float_as_uint(Ss[r0][kk + tig + 4]);
                a1[mt][3] = __float_as_uint(Ss[r0 + 8][kk + tig + 4]);
                a2[mt][0] = __float_as_uint(Kqs[r0][kk + tig]);
                a2[mt][1] = __float_as_uint(Kqs[r0 + 8][kk + tig]);
                a2[mt][2] = __float_as_uint(Kqs[r0][kk + tig + 4]);
                a2[mt][3] = __float_as_uint(Kqs[r0 + 8][kk + tig + 4]);
            }
#pragma unroll
            for (int nt = 0; nt < 2; nt++) {
                int cn = wn * 16 + nt * 8 + g;
                b1[nt][0] = __float_as_uint(P1[kk + tig][cn]);
                b1[nt][1] = __float_as_uint(P1[kk + tig + 4][cn]);
                b2[nt][0] = __float_as_uint(P2[kk + tig][cn]);
                b2[nt][1] = __float_as_uint(P2[kk + tig + 4][cn]);
            }
#pragma unroll
            for (int mt = 0; mt < 2; mt++)
#pragma unroll
                for (int nt = 0; nt < 2; nt++) {
                    mma8(val[p][mt][nt], a1[mt], b1[nt]);
                    mma8(val[p][mt][nt], a2[mt], b2[nt]);
                }
        }
        __syncthreads();
    }

    float scl4[4];
#pragma unroll
    for (int mt = 0; mt < 2; mt++)
#pragma unroll
        for (int h2 = 0; h2 < 2; h2++) {
            int row = wm * 32 + mt * 16 + h2 * 8 + g;
            float gc = gcum[rowbase + row];
            scl4[mt * 2 + h2] = rsqrtf(fmaxf(gc, 1.0f)) * INV_SQRT_P;
        }
    float s[4] = {}, s2[4] = {};
#pragma unroll
    for (int p = 0; p < 4; p++)
#pragma unroll
        for (int mt = 0; mt < 2; mt++)
#pragma unroll
            for (int nt = 0; nt < 2; nt++)
#pragma unroll
                for (int h2 = 0; h2 < 2; h2++) {
                    int row = wm * 32 + mt * 16 + h2 * 8 + g;
                    int col = p * 64 + wn * 16 + nt * 8 + 2 * tig;
                    int slot = mt * 2 + h2;
                    float2 cb = *reinterpret_cast<const float2*>(
                        &comb[(rowbase + row) * 256 + col]);
                    float v0 = cb.x + val[p][mt][nt][h2 * 2]     * scl4[slot];
                    float v1 = cb.y + val[p][mt][nt][h2 * 2 + 1] * scl4[slot];
                    val[p][mt][nt][h2 * 2] = v0;
                    val[p][mt][nt][h2 * 2 + 1] = v1;
                    s[slot] += v0 + v1;
                    s2[slot] += v0 * v0 + v1 * v1;
                }
#pragma unroll
    for (int o = 1; o <= 2; o <<= 1)
#pragma unroll
        for (int i = 0; i < 4; i++) {
            s[i]  += __shfl_xor_sync(0xffffffffu, s[i],  o);
            s2[i] += __shfl_xor_sync(0xffffffffu, s2[i], o);
        }
    if (tig == 0) {
#pragma unroll
        for (int mt = 0; mt < 2; mt++)
#pragma unroll
            for (int h2 = 0; h2 < 2; h2++) {
                int row = wm * 32 + mt * 16 + h2 * 8 + g;
                ws[wn][row]  = s[mt * 2 + h2];
                ws2[wn][row] = s2[mt * 2 + h2];
            }
    }
    __syncthreads();
    float mean4[4], rstd4[4];
#pragma unroll
    for (int mt = 0; mt < 2; mt++)
#pragma unroll
        for (int h2 = 0; h2 < 2; h2++) {
            int row = wm * 32 + mt * 16 + h2 * 8 + g;
            float St = ws[0][row] + ws[1][row] + ws[2][row] + ws[3][row];
            float S2t = ws2[0][row] + ws2[1][row] + ws2[2][row] + ws2[3][row];
            float mean = St * (1.0f / 256.0f);
            float var = S2t * (1.0f / 256.0f) - mean * mean;
            mean4[mt * 2 + h2] = mean;
            rstd4[mt * 2 + h2] = rsqrtf(var + 1e-5f);
        }
#pragma unroll
    for (int p = 0; p < 4; p++)
#pragma unroll
        for (int nt = 0; nt < 2; nt++) {
            int col = p * 64 + wn * 16 + nt * 8 + 2 * tig;
            float g0 = lng[col], g1 = lng[col + 1];
            float b0 = lnbv[col], b1 = lnbv[col + 1];
#pragma unroll
            for (int mt = 0; mt < 2; mt++)
#pragma unroll
                for (int h2 = 0; h2 < 2; h2++) {
                    int row = wm * 32 + mt * 16 + h2 * 8 + g;
                    int slot = mt * 2 + h2;
                    float v0 = (val[p][mt][nt][h2 * 2]     - mean4[slot]) * rstd4[slot] * g0 + b0;
                    float v1 = (val[p][mt][nt][h2 * 2 + 1] - mean4[slot]) * rstd4[slot] * g1 + b1;
                    *reinterpret_cast<float2*>(&outb[(rowbase + row) * 256 + col]) =
                        make_float2(v0, v1);
                }
        }
}

// ---------------- stream/event context (created once, outside capture) -----
namespace {
struct Ctx {
    cudaStream_t s1, s2;
    cudaEvent_t eR1, eR2, eGV, eA, eBC;
    Ctx() {
        cudaStreamCreateWithFlags(&s1, cudaStreamNonBlocking);
        cudaStreamCreateWithFlags(&s2, cudaStreamNonBlocking);
        cudaEventCreateWithFlags(&eR1, cudaEventDisableTiming);
        cudaEventCreateWithFlags(&eR2, cudaEventDisableTiming);
        cudaEventCreateWithFlags(&eGV, cudaEventDisableTiming);
        cudaEventCreateWithFlags(&eA, cudaEventDisableTiming);
        cudaEventCreateWithFlags(&eBC, cudaEventDisableTiming);
        cudaFuncSetAttribute(kv_pass3_mma_k,
                             cudaFuncAttributeMaxDynamicSharedMemorySize, (int)SMEM_P3);
        cudaFuncSetAttribute(tgemm_k<64, 32, 1, 2, 5, 0, 0>,
                             cudaFuncAttributeMaxDynamicSharedMemorySize, smemg(64, 32));
        cudaFuncSetAttribute(tgemm_k<64, 32, 1, 2, 1, 1, 0>,
                             cudaFuncAttributeMaxDynamicSharedMemorySize, smemg(64, 32));
        cudaFuncSetAttribute(tgemm_k<64, 32, 1, 2, 3, 1, 0>,
                             cudaFuncAttributeMaxDynamicSharedMemorySize, smemg(64, 32));
        cudaFuncSetAttribute(tgemm_k<128, 64, 2, 4, 0, 0, 0>,
                             cudaFuncAttributeMaxDynamicSharedMemorySize, smemg(128, 64));
        cudaFuncSetAttribute(tgemm_k<128, 64, 2, 4, 4, 0, 0>,
                             cudaFuncAttributeMaxDynamicSharedMemorySize, smemg(128, 64));
        cudaFuncSetAttribute(tgemm_k<128, 64, 2, 4, 2, 0, 1>,
                             cudaFuncAttributeMaxDynamicSharedMemorySize, smemg(128, 64));
    }
};
Ctx& C() { static Ctx c; return c; }
}

// ---------------- host launch -----------------------------------------------
extern "C" void kernel_launch(void* const* d_in, const int* in_sizes, int n_in,
                              void* d_out, int out_size)
{
    (void)in_sizes; (void)n_in; (void)out_size;
    const float* x        = (const float*)d_in[0];
    const float* pos_ph   = (const float*)d_in[1];
    const float* w_mem1v  = (const float*)d_in[2];
    const float* b_mem1v  = (const float*)d_in[3];
    const float* w_mem1o  = (const float*)d_in[4];
    const float* b_mem1o  = (const float*)d_in[5];
    const float* w_off    = (const float*)d_in[6];
    const float* b_off    = (const float*)d_in[7];
    const float* w_key    = (const float*)d_in[8];
    const float* b_key    = (const float*)d_in[9];
    const float* w_val    = (const float*)d_in[10];
    const float* b_val    = (const float*)d_in[11];
    const float* w_sk1    = (const float*)d_in[12];
    const float* b_sk1    = (const float*)d_in[13];
    const float* w_sk2    = (const float*)d_in[14];
    const float* b_sk2    = (const float*)d_in[15];
    const float* w_gate   = (const float*)d_in[16];
    const float* b_gate   = (const float*)d_in[17];
    const float* ln_g     = (const float*)d_in[18];
    const float* ln_b     = (const float*)d_in[19];
    const float* w_out    = (const float*)d_in[20];
    const float* b_out    = (const float*)d_in[21];
    float* out = (float*)d_out;

    float* buf = nullptr;
    cudaGetSymbolAddress((void**)&buf, g_buf);
    float* csum  = buf + OFF_CSUM;
    float* offp  = buf + OFF_OFFP;
    float* pcon  = buf + OFF_PCON;
    float* pc    = buf + OFF_PC;
    float* ps    = buf + OFF_PS;
    float* ac    = buf + OFF_AC;
    float* pr    = buf + OFF_POSRET;
    float* kq    = buf + OFF_KQ;
    float* u     = buf + OFF_U;
    float* gate  = buf + OFF_GATE;
    float* gcum  = buf + OFF_GCUM;
    float* gv    = buf + OFF_GV;
    float* ctx   = buf + OFF_CTX;
    float* h     = buf + OFF_H;
    float* csum2 = buf + OFF_CSUM2;
    float* dS    = buf + OFF_DS;
    float* comb  = buf + OFF_COMB;
    float* lnb   = buf + OFF_LN;

    Ctx& c = C();
    dim3 gS(1, Mc / 64);
    dim3 gW(4, Mc / 128);
    const int SS = smemg(64, 32), SW = smemg(128, 64);

    // fork
    cudaEventRecord(c.eR1, 0);
    cudaStreamWaitEvent(c.s1, c.eR1, 0);
    cudaEventRecord(c.eR2, 0);
    cudaStreamWaitEvent(c.s2, c.eR2, 0);

    // ---- path A (s1): mem1 ----
    pos_pre_k<<<(Lc * Pc) / 256, 256, 0, c.s1>>>(pos_ph, w_off, b_off, pc, ps, pcon);
    tgemm_k<64, 32, 1, 2, 5, 0, 0><<<gS, 256, SS, c.s1>>>(x, nullptr, w_mem1v, b_mem1v, pc, ps, ac, Pc, Dc);
    tgemm_k<64, 32, 1, 2, 1, 1, 0><<<gS, 256, SS, c.s1>>>(x, nullptr, w_off, nullptr, pcon, nullptr, offp, Pc, Dc);
    scan_chunk_sums_k<<<Bc * NCc, 64, 0, c.s1>>>(ac, csum2, 64, 64);
    scan_prefix_k<<<Bc, 64, 0, c.s1>>>(csum2, 64);
    scan_apply_posret_k<<<Bc * NCc, 64, 0, c.s1>>>(ac, csum2, offp, pc, ps, pr);
    tgemm_k<128, 64, 2, 4, 0, 0, 0><<<gW, 256, SW, c.s1>>>(pr, nullptr, w_mem1o, b_mem1o, nullptr, nullptr, comb, Dc, Pc);
    cudaEventRecord(c.eA, c.s1);

    // ---- path B/C (s2): gate, values, keys ----
    gate_k<<<Mc / 8, 256, 0, c.s2>>>(x, w_gate, b_gate, gate);
    tgemm_k<128, 64, 2, 4, 4, 0, 0><<<gW, 256, SW, c.s2>>>(x, nullptr, w_val, b_val, gate, nullptr, gv, Dc, Dc);
    cudaEventRecord(c.eGV, c.s2);
    gate_scan_k<<<Bc, 32, 0, c.s2>>>(gate, gcum);
    tgemm_k<64, 32, 1, 2, 3, 1, 0><<<gS, 256, SS, c.s2>>>(x, nullptr, w_key, b_key, nullptr, nullptr, kq, Pc, Dc);
    cudaEventRecord(c.eBC, c.s2);

    // ---- path D (default): storage phases + attention ----
    xscan_sums_k<<<Bc * NC2, 256>>>(x, csum);
    xscan_prefix_k<<<Bc, 256>>>(csum);
    xscan_apply_k<<<Bc * NC2, 256>>>(x, csum, ctx);
    tgemm_k<128, 64, 2, 4, 2, 0, 1><<<gW, 256, SW>>>(x, ctx, w_sk1, b_sk1, nullptr, nullptr, h, Dc, 2 * Dc);
    tgemm_k<64, 32, 1, 2, 3, 1, 0><<<gS, 256, SS>>>(h, nullptr, w_sk2, b_sk2, nullptr, nullptr, u, Pc, Dc);
    cudaStreamWaitEvent(0, c.eGV, 0);
    chunk_delta_k<<<Bc * NCc, 256>>>(u, gv, dS);
    state_prefix_k<<<(Bc * 64 * 256) / 256, 256>>>(dS);
    cudaStreamWaitEvent(0, c.eA, 0);
    cudaStreamWaitEvent(0, c.eBC, 0);
    kv_pass3_mma_k<<<Bc * NCc, 256, SMEM_P3>>>(kq, u, gv, dS, gcum, comb, ln_g, ln_b, lnb);
    tgemm_k<128, 64, 2, 4, 0, 0, 0><<<gW, 256, SW>>>(lnb, nullptr, w_out, b_out, nullptr, x, out, Dc, Dc);
}